// round 3
// baseline (speedup 1.0000x reference)
#include <cuda_runtime.h>

// EpochMixer: fused 2-layer transformer over 32768 independent 4-token sequences.
// R2: double-buffered cp.async weight staging chained across all GEMMs,
//     4-lane LayerNorm. FMA engine unchanged (f32x2 packed).

#define NSEQ   32768
#define GSEQ   16
#define TOK    64
#define DDIM   128
#define FDIM   512
#define NLAYER 2
#define NTHR   256
#define LNEPS  1e-5f

typedef unsigned long long u64;

struct SMem {
    float xs[TOK][DDIM + 4];
    float qs[TOK][DDIM + 4];
    float ks[TOK][DDIM + 4];
    float vs[TOK][DDIM + 4];
    float cb[TOK][DDIM + 4];
    float ws[2][DDIM][36];     // double-buffered 128x32 weight tiles
};

__device__ __forceinline__ void fma2(u64 &d, u64 a, u64 b) {
    asm("fma.rn.f32x2 %0, %1, %2, %0;" : "+l"(d) : "l"(a), "l"(b));
}

__device__ __forceinline__ float pairsum(u64 v) {
    float lo = __uint_as_float((unsigned)(v & 0xffffffffULL));
    float hi = __uint_as_float((unsigned)(v >> 32));
    return lo + hi;
}

__device__ __forceinline__ float gelu_exact(float v) {
    return 0.5f * v * (1.0f + erff(v * 0.70710678118654752f));
}

__device__ __forceinline__ void cp_commit() {
    asm volatile("cp.async.commit_group;" ::: "memory");
}

// stage 128 cols x 32 k of weights into buf via cp.async (16B each, 4/thread)
__device__ __forceinline__ void stage_tile(float (*buf)[36],
                                           const float* __restrict__ Wg,
                                           int ldw, int dc, int tid)
{
#pragma unroll
    for (int u = 0; u < 4; u++) {
        int idx = u * NTHR + tid;          // 0..1023
        int col = idx >> 3;
        int d4  = (idx & 7) << 2;
        unsigned sa = (unsigned)__cvta_generic_to_shared(&buf[col][d4]);
        asm volatile("cp.async.cg.shared.global [%0], [%1], 16;"
                     :: "r"(sa), "l"(Wg + (long)col * ldw + dc + d4) : "memory");
    }
}

// acc[4][8] += A[64][128] @ Wg^T.
// Precondition: chunk0 of Wg already staged into ws2[0] + committed.
// Postcondition: if nextW, its chunk0 staged into ws2[0] + committed (pending).
__device__ __forceinline__ void mm_acc(
    const float (*A)[DDIM + 4], const float* __restrict__ Wg, int ldw,
    const float* __restrict__ nextW, int nldw,
    float (*ws2)[DDIM][36], float acc[4][8], int tid)
{
    const int ty = tid >> 4;
    const int tx = tid & 15;

    u64 acc2[4][8];
#pragma unroll
    for (int i = 0; i < 4; i++)
#pragma unroll
        for (int j = 0; j < 8; j++) acc2[i][j] = 0ULL;

#pragma unroll
    for (int c = 0; c < 4; c++) {
        if (c < 3) {
            stage_tile(ws2[(c + 1) & 1], Wg, ldw, (c + 1) * 32, tid);
            cp_commit();
            asm volatile("cp.async.wait_group 1;" ::: "memory");
        } else if (nextW) {
            stage_tile(ws2[0], nextW, nldw, 0, tid);
            cp_commit();
            asm volatile("cp.async.wait_group 1;" ::: "memory");
        } else {
            asm volatile("cp.async.wait_group 0;" ::: "memory");
        }
        __syncthreads();

        const float (*wb)[36] = ws2[c & 1];
        const int dc = c * 32;
#pragma unroll
        for (int dd = 0; dd < 32; dd += 4) {
            ulonglong2 av[4], wv[8];
#pragma unroll
            for (int i = 0; i < 4; i++)
                av[i] = *(const ulonglong2*)&A[ty + 16 * i][dc + dd];
#pragma unroll
            for (int j = 0; j < 8; j++)
                wv[j] = *(const ulonglong2*)&wb[tx + 16 * j][dd];
#pragma unroll
            for (int i = 0; i < 4; i++)
#pragma unroll
                for (int j = 0; j < 8; j++) {
                    fma2(acc2[i][j], av[i].x, wv[j].x);
                    fma2(acc2[i][j], av[i].y, wv[j].y);
                }
        }
        __syncthreads();
    }
#pragma unroll
    for (int i = 0; i < 4; i++)
#pragma unroll
        for (int j = 0; j < 8; j++) acc[i][j] += pairsum(acc2[i][j]);
}

// LayerNorm, 4 lanes per row (64 rows x 4 lanes = 256 threads)
__device__ __forceinline__ void lnorm4(float (*x)[DDIM + 4],
                                       const float* __restrict__ g,
                                       const float* __restrict__ b, int tid)
{
    int row = tid >> 2;
    int c0  = (tid & 3) << 5;            // 32 cols per lane
    float4 v[8];
    float s = 0.0f;
#pragma unroll
    for (int i = 0; i < 8; i++) {
        v[i] = *(float4*)&x[row][c0 + i * 4];
        s += v[i].x + v[i].y + v[i].z + v[i].w;
    }
    s += __shfl_xor_sync(0xffffffffu, s, 1);
    s += __shfl_xor_sync(0xffffffffu, s, 2);
    float mu = s * (1.0f / 128.0f);
    float q = 0.0f;
#pragma unroll
    for (int i = 0; i < 8; i++) {
        v[i].x -= mu; v[i].y -= mu; v[i].z -= mu; v[i].w -= mu;
        q += v[i].x * v[i].x + v[i].y * v[i].y + v[i].z * v[i].z + v[i].w * v[i].w;
    }
    q += __shfl_xor_sync(0xffffffffu, q, 1);
    q += __shfl_xor_sync(0xffffffffu, q, 2);
    float inv = rsqrtf(q * (1.0f / 128.0f) + LNEPS);
#pragma unroll
    for (int i = 0; i < 8; i++) {
        int c = c0 + i * 4;
        v[i].x = v[i].x * inv * g[c + 0] + b[c + 0];
        v[i].y = v[i].y * inv * g[c + 1] + b[c + 1];
        v[i].z = v[i].z * inv * g[c + 2] + b[c + 2];
        v[i].w = v[i].w * inv * g[c + 3] + b[c + 3];
        *(float4*)&x[row][c] = v[i];
    }
}

__global__ void __launch_bounds__(NTHR, 1)
epochmixer_kernel(const float* __restrict__ z0, const float* __restrict__ z1,
                  const float* __restrict__ z2, const float* __restrict__ cls,
                  const float* __restrict__ Wqkv, const float* __restrict__ bqkv,
                  const float* __restrict__ Wo,  const float* __restrict__ bo,
                  const float* __restrict__ W1,  const float* __restrict__ b1,
                  const float* __restrict__ W2,  const float* __restrict__ b2,
                  const float* __restrict__ ln1g, const float* __restrict__ ln1b,
                  const float* __restrict__ ln2g, const float* __restrict__ ln2b,
                  float* __restrict__ out)
{
    extern __shared__ char smraw[];
    SMem &sm = *reinterpret_cast<SMem*>(smraw);

    const int tid  = threadIdx.x;
    const int ty   = tid >> 4;
    const int tx   = tid & 15;
    const int seq0 = blockIdx.x * GSEQ;

    // prefetch first Wqkv chunk while loading tokens
    stage_tile(sm.ws[0], Wqkv, DDIM, 0, tid);
    cp_commit();

    // ---- load tokens: row = g*4+s; s=0 CLS, s=1..3 -> z_{s-1}[seq0+g] ----
#pragma unroll
    for (int u = 0; u < 8; u++) {
        int idx = u * NTHR + tid;
        int row = idx >> 5;
        int c4  = (idx & 31) << 2;
        int g   = row >> 2, s = row & 3;
        float4 v;
        if (s == 0) {
            v = *(const float4*)(cls + c4);
        } else {
            const float* zp = (s == 1) ? z0 : (s == 2) ? z1 : z2;
            v = *(const float4*)(zp + (long)(seq0 + g) * DDIM + c4);
        }
        *(float4*)&sm.xs[row][c4] = v;
    }
    // no sync needed: mm_acc's first wait+sync publishes both xs and chunk0

    for (int l = 0; l < NLAYER; l++) {
        const float* Wqkv_l = Wqkv + (long)l * 3 * DDIM * DDIM;
        const float* bqkv_l = bqkv + l * 3 * DDIM;
        const float* Wo_l   = Wo   + (long)l * DDIM * DDIM;
        const float* bo_l   = bo   + l * DDIM;
        const float* W1_l   = W1   + (long)l * FDIM * DDIM;
        const float* b1_l   = b1   + l * FDIM;
        const float* W2_l   = W2   + (long)l * DDIM * FDIM;
        const float* b2_l   = b2   + l * DDIM;

        // ---- QKV projections (chained prefetch Q->K->V->Wo) ----
        for (int p = 0; p < 3; p++) {
            const float* Wg   = Wqkv_l + (long)p * DDIM * DDIM;
            const float* Wnxt = (p < 2) ? Wg + DDIM * DDIM : Wo_l;
            float acc[4][8];
#pragma unroll
            for (int i = 0; i < 4; i++)
#pragma unroll
                for (int j = 0; j < 8; j++) acc[i][j] = 0.0f;
            mm_acc(sm.xs, Wg, DDIM, Wnxt, DDIM, sm.ws, acc, tid);
            float (*dst)[DDIM + 4] = (p == 0) ? sm.qs : (p == 1) ? sm.ks : sm.vs;
            const float* bp = bqkv_l + p * DDIM;
#pragma unroll
            for (int i = 0; i < 4; i++)
#pragma unroll
                for (int j = 0; j < 8; j++) {
                    int row = ty + 16 * i, col = tx + 16 * j;
                    dst[row][col] = acc[i][j] + bp[col];
                }
        }
        __syncthreads();

        // ---- attention: one thread per (local seq, head); S=4, dh=16 ----
        if (tid < 128) {
            int g = tid >> 3, h = tid & 7;
            int r0 = g * 4, co = h * 16;
            float sc[4][4];
#pragma unroll
            for (int i = 0; i < 4; i++)
#pragma unroll
                for (int j = 0; j < 4; j++) {
                    float s = 0.0f;
#pragma unroll
                    for (int e = 0; e < 16; e++)
                        s += sm.qs[r0 + i][co + e] * sm.ks[r0 + j][co + e];
                    sc[i][j] = s * 0.25f;
                }
#pragma unroll
            for (int i = 0; i < 4; i++) {
                float m = sc[i][0];
#pragma unroll
                for (int j = 1; j < 4; j++) m = fmaxf(m, sc[i][j]);
                float den = 0.0f;
#pragma unroll
                for (int j = 0; j < 4; j++) {
                    sc[i][j] = expf(sc[i][j] - m);
                    den += sc[i][j];
                }
                float inv = 1.0f / den;
#pragma unroll
                for (int j = 0; j < 4; j++) sc[i][j] *= inv;
            }
#pragma unroll
            for (int i = 0; i < 4; i++)
#pragma unroll
                for (int e = 0; e < 16; e++) {
                    float o = 0.0f;
#pragma unroll
                    for (int j = 0; j < 4; j++)
                        o += sc[i][j] * sm.vs[r0 + j][co + e];
                    sm.cb[r0 + i][co + e] = o;
                }
        }
        // cb published by Wo mm_acc's first sync

        // ---- output projection + residual, LN1 ----
        {
            float acc[4][8];
#pragma unroll
            for (int i = 0; i < 4; i++)
#pragma unroll
                for (int j = 0; j < 8; j++) acc[i][j] = 0.0f;
            mm_acc(sm.cb, Wo_l, DDIM, W1_l, DDIM, sm.ws, acc, tid);
#pragma unroll
            for (int i = 0; i < 4; i++)
#pragma unroll
                for (int j = 0; j < 8; j++) {
                    int row = ty + 16 * i, col = tx + 16 * j;
                    sm.xs[row][col] += acc[i][j] + bo_l[col];
                }
        }
        __syncthreads();
        lnorm4(sm.xs, ln1g + l * DDIM, ln1b + l * DDIM, tid);
        __syncthreads();

        // ---- FFN ----
        float facc[4][8];
#pragma unroll
        for (int i = 0; i < 4; i++)
#pragma unroll
            for (int j = 0; j < 8; j++) facc[i][j] = 0.0f;

        for (int fc = 0; fc < 4; fc++) {
            float hacc[4][8];
#pragma unroll
            for (int i = 0; i < 4; i++)
#pragma unroll
                for (int j = 0; j < 8; j++) hacc[i][j] = 0.0f;
            // h = gelu(x @ W1_chunk^T); next = matching W2 chunk
            mm_acc(sm.xs, W1_l + (long)fc * 128 * DDIM, DDIM,
                   W2_l + fc * 128, FDIM, sm.ws, hacc, tid);
            const float* b1p = b1_l + fc * 128;
#pragma unroll
            for (int i = 0; i < 4; i++)
#pragma unroll
                for (int j = 0; j < 8; j++) {
                    int row = ty + 16 * i, col = tx + 16 * j;
                    sm.cb[row][col] = gelu_exact(hacc[i][j] + b1p[col]);
                }
            // next after W2@fc: W1@fc+1, or next layer's Wqkv, or none
            const float* Wnxt;
            int nldw = DDIM;
            if (fc < 3)       Wnxt = W1_l + (long)(fc + 1) * 128 * DDIM;
            else if (l == 0)  Wnxt = Wqkv + (long)3 * DDIM * DDIM;  // layer 1 Wq
            else              Wnxt = nullptr;
            mm_acc(sm.cb, W2_l + fc * 128, FDIM, Wnxt, nldw, sm.ws, facc, tid);
        }
#pragma unroll
        for (int i = 0; i < 4; i++)
#pragma unroll
            for (int j = 0; j < 8; j++) {
                int row = ty + 16 * i, col = tx + 16 * j;
                sm.xs[row][col] += facc[i][j] + b2_l[col];
            }
        __syncthreads();
        lnorm4(sm.xs, ln2g + l * DDIM, ln2b + l * DDIM, tid);
        __syncthreads();
    }

    // ---- write CLS tokens ----
#pragma unroll
    for (int u = 0; u < 2; u++) {
        int idx = u * NTHR + tid;
        int g   = idx >> 5;
        int c4  = (idx & 31) << 2;
        *(float4*)(out + (long)(seq0 + g) * DDIM + c4) = *(float4*)&sm.xs[g * 4][c4];
    }
}

extern "C" void kernel_launch(void* const* d_in, const int* in_sizes, int n_in,
                              void* d_out, int out_size)
{
    (void)in_sizes; (void)n_in; (void)out_size;
    const float* z0   = (const float*)d_in[0];
    const float* z1   = (const float*)d_in[1];
    const float* z2   = (const float*)d_in[2];
    const float* cls  = (const float*)d_in[3];
    const float* Wqkv = (const float*)d_in[4];
    const float* bqkv = (const float*)d_in[5];
    const float* Wo   = (const float*)d_in[6];
    const float* bo   = (const float*)d_in[7];
    const float* W1   = (const float*)d_in[8];
    const float* b1   = (const float*)d_in[9];
    const float* W2   = (const float*)d_in[10];
    const float* b2   = (const float*)d_in[11];
    const float* ln1g = (const float*)d_in[12];
    const float* ln1b = (const float*)d_in[13];
    const float* ln2g = (const float*)d_in[14];
    const float* ln2b = (const float*)d_in[15];
    float* out = (float*)d_out;

    cudaFuncSetAttribute(epochmixer_kernel,
                         cudaFuncAttributeMaxDynamicSharedMemorySize,
                         (int)sizeof(SMem));
    epochmixer_kernel<<<NSEQ / GSEQ, NTHR, sizeof(SMem)>>>(
        z0, z1, z2, cls, Wqkv, bqkv, Wo, bo, W1, b1, W2, b2,
        ln1g, ln1b, ln2g, ln2b, out);
}

// round 5
// speedup vs baseline: 1.0186x; 1.0186x over previous
#include <cuda_runtime.h>

// EpochMixer: fused 2-layer transformer over 32768 independent 4-token sequences.
// R3: bank-conflict-free XOR-swizzled weight tiles (stride 32 floats),
//     3-buffer cp.async ring with ONE barrier per 32-k chunk, chained across
//     all 24 GEMMs. f32x2 packed FMA engine unchanged.

#define NSEQ   32768
#define GSEQ   16
#define TOK    64
#define DDIM   128
#define FDIM   512
#define NLAYER 2
#define NTHR   256
#define LNEPS  1e-5f

typedef unsigned long long u64;

struct SMem {
    float xs[TOK][DDIM + 4];
    float qs[TOK][DDIM + 4];
    float ks[TOK][DDIM + 4];
    float vs[TOK][DDIM + 4];
    float cb[TOK][DDIM + 4];
    float ws[3][DDIM][32];     // 3-buffer ring, swizzled 128x32 weight tiles
};

__device__ __forceinline__ void fma2(u64 &d, u64 a, u64 b) {
    asm("fma.rn.f32x2 %0, %1, %2, %0;" : "+l"(d) : "l"(a), "l"(b));
}

__device__ __forceinline__ float pairsum(u64 v) {
    float lo = __uint_as_float((unsigned)(v & 0xffffffffULL));
    float hi = __uint_as_float((unsigned)(v >> 32));
    return lo + hi;
}

__device__ __forceinline__ float gelu_exact(float v) {
    return 0.5f * v * (1.0f + erff(v * 0.70710678118654752f));
}

__device__ __forceinline__ void cp_commit() {
    asm volatile("cp.async.commit_group;" ::: "memory");
}
template <int N>
__device__ __forceinline__ void cp_wait() {
    asm volatile("cp.async.wait_group %0;" :: "n"(N) : "memory");
}

// stage 128 cols x 32 k of weights into swizzled buf via cp.async (16B, 4/thr).
// 16B group gd of row col lands at slot gd ^ (col & 7).
__device__ __forceinline__ void stage_tile(float (*buf)[32],
                                           const float* __restrict__ Wg,
                                           int ldw, int dc, int tid)
{
#pragma unroll
    for (int u = 0; u < 4; u++) {
        int idx = u * NTHR + tid;          // 0..1023
        int col = idx >> 3;
        int gd  = idx & 7;
        int slot = (gd ^ (col & 7)) << 2;
        unsigned sa = (unsigned)__cvta_generic_to_shared(&buf[col][slot]);
        asm volatile("cp.async.cg.shared.global [%0], [%1], 16;"
                     :: "r"(sa), "l"(Wg + (long)col * ldw + dc + (gd << 2)) : "memory");
    }
}

// acc[4][8] += A[64][128] @ Wg^T  (Wg row-major, rows=out cols, ldw stride).
// Ring invariant on entry: chunk0 of Wg staged into ws3[rb], committed, and it
// is the ONLY outstanding cp.async group. On exit (nextW != null): chunk0 of
// nextW staged into ws3[(rb+1)%3], sole outstanding group; rb advanced.
__device__ __forceinline__ void mm_acc(
    const float (*A)[DDIM + 4], const float* __restrict__ Wg, int ldw,
    const float* __restrict__ nextW, int nldw,
    float (*ws3)[DDIM][32], float acc[4][8], int tid, int &rb)
{
    const int ty = tid >> 4;
    const int tx = tid & 15;
    const int sw = tx & 7;

    // stage chunk1 into ring slot rb+1  (pending: ch0, ch1)
    stage_tile(ws3[(rb + 1) % 3], Wg, ldw, 32, tid);
    cp_commit();

    u64 acc2[4][8];
#pragma unroll
    for (int i = 0; i < 4; i++)
#pragma unroll
        for (int j = 0; j < 8; j++) acc2[i][j] = 0ULL;

#pragma unroll
    for (int c = 0; c < 4; c++) {
        if (c < 3 || nextW) cp_wait<1>(); else cp_wait<0>();
        __syncthreads();                       // chunk c visible to all

        const float (*wb)[32] = ws3[(rb + c) % 3];
        const int dc = c * 32;
#pragma unroll
        for (int dd = 0; dd < 32; dd += 4) {
            const int g = dd >> 2;
            ulonglong2 av[4], wv[8];
#pragma unroll
            for (int i = 0; i < 4; i++)
                av[i] = *(const ulonglong2*)&A[ty + 16 * i][dc + dd];
#pragma unroll
            for (int j = 0; j < 8; j++)
                wv[j] = *(const ulonglong2*)&wb[tx + 16 * j][(g ^ sw) << 2];
#pragma unroll
            for (int i = 0; i < 4; i++)
#pragma unroll
                for (int j = 0; j < 8; j++) {
                    fma2(acc2[i][j], av[i].x, wv[j].x);
                    fma2(acc2[i][j], av[i].y, wv[j].y);
                }
        }

        // stage chunk c+2 (or next GEMM's chunk0) into ring slot rb+c+2.
        // Safe: sync above guarantees everyone is done reading that slot.
        if (c < 2) {
            stage_tile(ws3[(rb + c + 2) % 3], Wg, ldw, (c + 2) * 32, tid);
            cp_commit();
        } else if (c == 2 && nextW) {
            stage_tile(ws3[(rb + 4) % 3], nextW, nldw, 0, tid);
            cp_commit();
        }
    }
    rb = (rb + 4) % 3;   // == rb+1: next GEMM's chunk0 slot

#pragma unroll
    for (int i = 0; i < 4; i++)
#pragma unroll
        for (int j = 0; j < 8; j++) acc[i][j] += pairsum(acc2[i][j]);
}

// LayerNorm, 4 lanes per row (64 rows x 4 lanes = 256 threads)
__device__ __forceinline__ void lnorm4(float (*x)[DDIM + 4],
                                       const float* __restrict__ g,
                                       const float* __restrict__ b, int tid)
{
    int row = tid >> 2;
    int c0  = (tid & 3) << 5;
    float4 v[8];
    float s = 0.0f;
#pragma unroll
    for (int i = 0; i < 8; i++) {
        v[i] = *(float4*)&x[row][c0 + i * 4];
        s += v[i].x + v[i].y + v[i].z + v[i].w;
    }
    s += __shfl_xor_sync(0xffffffffu, s, 1);
    s += __shfl_xor_sync(0xffffffffu, s, 2);
    float mu = s * (1.0f / 128.0f);
    float q = 0.0f;
#pragma unroll
    for (int i = 0; i < 8; i++) {
        v[i].x -= mu; v[i].y -= mu; v[i].z -= mu; v[i].w -= mu;
        q += v[i].x * v[i].x + v[i].y * v[i].y + v[i].z * v[i].z + v[i].w * v[i].w;
    }
    q += __shfl_xor_sync(0xffffffffu, q, 1);
    q += __shfl_xor_sync(0xffffffffu, q, 2);
    float inv = rsqrtf(q * (1.0f / 128.0f) + LNEPS);
#pragma unroll
    for (int i = 0; i < 8; i++) {
        int c = c0 + i * 4;
        v[i].x = v[i].x * inv * g[c + 0] + b[c + 0];
        v[i].y = v[i].y * inv * g[c + 1] + b[c + 1];
        v[i].z = v[i].z * inv * g[c + 2] + b[c + 2];
        v[i].w = v[i].w * inv * g[c + 3] + b[c + 3];
        *(float4*)&x[row][c] = v[i];
    }
}

__global__ void __launch_bounds__(NTHR, 1)
epochmixer_kernel(const float* __restrict__ z0, const float* __restrict__ z1,
                  const float* __restrict__ z2, const float* __restrict__ cls,
                  const float* __restrict__ Wqkv, const float* __restrict__ bqkv,
                  const float* __restrict__ Wo,  const float* __restrict__ bo,
                  const float* __restrict__ W1,  const float* __restrict__ b1,
                  const float* __restrict__ W2,  const float* __restrict__ b2,
                  const float* __restrict__ ln1g, const float* __restrict__ ln1b,
                  const float* __restrict__ ln2g, const float* __restrict__ ln2b,
                  float* __restrict__ out)
{
    extern __shared__ char smraw[];
    SMem &sm = *reinterpret_cast<SMem*>(smraw);

    const int tid  = threadIdx.x;
    const int ty   = tid >> 4;
    const int tx   = tid & 15;
    const int seq0 = blockIdx.x * GSEQ;
    int rb = 0;

    // prefetch first Wqkv chunk0 into ring slot 0 while loading tokens
    stage_tile(sm.ws[0], Wqkv, DDIM, 0, tid);
    cp_commit();

    // ---- load tokens: row = g*4+s; s=0 CLS, s=1..3 -> z_{s-1}[seq0+g] ----
#pragma unroll
    for (int u = 0; u < 8; u++) {
        int idx = u * NTHR + tid;
        int row = idx >> 5;
        int c4  = (idx & 31) << 2;
        int g   = row >> 2, s = row & 3;
        float4 v;
        if (s == 0) {
            v = *(const float4*)(cls + c4);
        } else {
            const float* zp = (s == 1) ? z0 : (s == 2) ? z1 : z2;
            v = *(const float4*)(zp + (long)(seq0 + g) * DDIM + c4);
        }
        *(float4*)&sm.xs[row][c4] = v;
    }
    // xs published by first mm_acc's iter-0 barrier

    for (int l = 0; l < NLAYER; l++) {
        const float* Wqkv_l = Wqkv + (long)l * 3 * DDIM * DDIM;
        const float* bqkv_l = bqkv + l * 3 * DDIM;
        const float* Wo_l   = Wo   + (long)l * DDIM * DDIM;
        const float* bo_l   = bo   + l * DDIM;
        const float* W1_l   = W1   + (long)l * FDIM * DDIM;
        const float* b1_l   = b1   + l * FDIM;
        const float* W2_l   = W2   + (long)l * DDIM * FDIM;
        const float* b2_l   = b2   + l * DDIM;

        // ---- QKV projections (chained prefetch Q->K->V->Wo) ----
        for (int p = 0; p < 3; p++) {
            const float* Wg   = Wqkv_l + (long)p * DDIM * DDIM;
            const float* Wnxt = (p < 2) ? Wg + DDIM * DDIM : Wo_l;
            float acc[4][8];
#pragma unroll
            for (int i = 0; i < 4; i++)
#pragma unroll
                for (int j = 0; j < 8; j++) acc[i][j] = 0.0f;
            mm_acc(sm.xs, Wg, DDIM, Wnxt, DDIM, sm.ws, acc, tid, rb);
            float (*dst)[DDIM + 4] = (p == 0) ? sm.qs : (p == 1) ? sm.ks : sm.vs;
            const float* bp = bqkv_l + p * DDIM;
#pragma unroll
            for (int i = 0; i < 4; i++)
#pragma unroll
                for (int j = 0; j < 8; j++) {
                    int row = ty + 16 * i, col = tx + 16 * j;
                    dst[row][col] = acc[i][j] + bp[col];
                }
        }
        __syncthreads();

        // ---- attention: one thread per (local seq, head); S=4, dh=16 ----
        if (tid < 128) {
            int g = tid >> 3, h = tid & 7;
            int r0 = g * 4, co = h * 16;
            float sc[4][4];
#pragma unroll
            for (int i = 0; i < 4; i++)
#pragma unroll
                for (int j = 0; j < 4; j++) {
                    float s = 0.0f;
#pragma unroll
                    for (int e = 0; e < 16; e++)
                        s += sm.qs[r0 + i][co + e] * sm.ks[r0 + j][co + e];
                    sc[i][j] = s * 0.25f;
                }
#pragma unroll
            for (int i = 0; i < 4; i++) {
                float m = sc[i][0];
#pragma unroll
                for (int j = 1; j < 4; j++) m = fmaxf(m, sc[i][j]);
                float den = 0.0f;
#pragma unroll
                for (int j = 0; j < 4; j++) {
                    sc[i][j] = expf(sc[i][j] - m);
                    den += sc[i][j];
                }
                float inv = 1.0f / den;
#pragma unroll
                for (int j = 0; j < 4; j++) sc[i][j] *= inv;
            }
#pragma unroll
            for (int i = 0; i < 4; i++)
#pragma unroll
                for (int e = 0; e < 16; e++) {
                    float o = 0.0f;
#pragma unroll
                    for (int j = 0; j < 4; j++)
                        o += sc[i][j] * sm.vs[r0 + j][co + e];
                    sm.cb[r0 + i][co + e] = o;
                }
        }
        // cb published by Wo mm_acc's iter-0 barrier

        // ---- output projection + residual, LN1 ----
        {
            float acc[4][8];
#pragma unroll
            for (int i = 0; i < 4; i++)
#pragma unroll
                for (int j = 0; j < 8; j++) acc[i][j] = 0.0f;
            mm_acc(sm.cb, Wo_l, DDIM, W1_l, DDIM, sm.ws, acc, tid, rb);
#pragma unroll
            for (int i = 0; i < 4; i++)
#pragma unroll
                for (int j = 0; j < 8; j++) {
                    int row = ty + 16 * i, col = tx + 16 * j;
                    sm.xs[row][col] += acc[i][j] + bo_l[col];
                }
        }
        __syncthreads();
        lnorm4(sm.xs, ln1g + l * DDIM, ln1b + l * DDIM, tid);
        __syncthreads();

        // ---- FFN: 4 chunks of 128 ----
        float facc[4][8];
#pragma unroll
        for (int i = 0; i < 4; i++)
#pragma unroll
            for (int j = 0; j < 8; j++) facc[i][j] = 0.0f;

        for (int fc = 0; fc < 4; fc++) {
            float hacc[4][8];
#pragma unroll
            for (int i = 0; i < 4; i++)
#pragma unroll
                for (int j = 0; j < 8; j++) hacc[i][j] = 0.0f;
            mm_acc(sm.xs, W1_l + (long)fc * 128 * DDIM, DDIM,
                   W2_l + fc * 128, FDIM, sm.ws, hacc, tid, rb);
            const float* b1p = b1_l + fc * 128;
#pragma unroll
            for (int i = 0; i < 4; i++)
#pragma unroll
                for (int j = 0; j < 8; j++) {
                    int row = ty + 16 * i, col = tx + 16 * j;
                    sm.cb[row][col] = gelu_exact(hacc[i][j] + b1p[col]);
                }
            const float* Wnxt;
            if (fc < 3)       Wnxt = W1_l + (long)(fc + 1) * 128 * DDIM;
            else if (l == 0)  Wnxt = Wqkv + (long)3 * DDIM * DDIM;
            else              Wnxt = nullptr;
            mm_acc(sm.cb, W2_l + fc * 128, FDIM, Wnxt, DDIM, sm.ws, facc, tid, rb);
        }
#pragma unroll
        for (int i = 0; i < 4; i++)
#pragma unroll
            for (int j = 0; j < 8; j++) {
                int row = ty + 16 * i, col = tx + 16 * j;
                sm.xs[row][col] += facc[i][j] + b2_l[col];
            }
        __syncthreads();
        lnorm4(sm.xs, ln2g + l * DDIM, ln2b + l * DDIM, tid);
        __syncthreads();
    }

    // ---- write CLS tokens ----
#pragma unroll
    for (int u = 0; u < 2; u++) {
        int idx = u * NTHR + tid;
        int g   = idx >> 5;
        int c4  = (idx & 31) << 2;
        *(float4*)(out + (long)(seq0 + g) * DDIM + c4) = *(float4*)&sm.xs[g * 4][c4];
    }
}

extern "C" void kernel_launch(void* const* d_in, const int* in_sizes, int n_in,
                              void* d_out, int out_size)
{
    (void)in_sizes; (void)n_in; (void)out_size;
    const float* z0   = (const float*)d_in[0];
    const float* z1   = (const float*)d_in[1];
    const float* z2   = (const float*)d_in[2];
    const float* cls  = (const float*)d_in[3];
    const float* Wqkv = (const float*)d_in[4];
    const float* bqkv = (const float*)d_in[5];
    const float* Wo   = (const float*)d_in[6];
    const float* bo   = (const float*)d_in[7];
    const float* W1   = (const float*)d_in[8];
    const float* b1   = (const float*)d_in[9];
    const float* W2   = (const float*)d_in[10];
    const float* b2   = (const float*)d_in[11];
    const float* ln1g = (const float*)d_in[12];
    const float* ln1b = (const float*)d_in[13];
    const float* ln2g = (const float*)d_in[14];
    const float* ln2b = (const float*)d_in[15];
    float* out = (float*)d_out;

    cudaFuncSetAttribute(epochmixer_kernel,
                         cudaFuncAttributeMaxDynamicSharedMemorySize,
                         (int)sizeof(SMem));
    epochmixer_kernel<<<NSEQ / GSEQ, NTHR, sizeof(SMem)>>>(
        z0, z1, z2, cls, Wqkv, bqkv, Wo, bo, W1, b1, W2, b2,
        ln1g, ln1b, ln2g, ln2b, out);
}

// round 6
// speedup vs baseline: 1.0192x; 1.0006x over previous
#include <cuda_runtime.h>

// EpochMixer: fused 2-layer transformer over 32768 independent 4-token sequences.
// R3: bank-conflict-free XOR-swizzled weight tiles (stride 32 floats),
//     3-buffer cp.async ring with ONE barrier per 32-k chunk, chained across
//     all 24 GEMMs. f32x2 packed FMA engine unchanged.

#define NSEQ   32768
#define GSEQ   16
#define TOK    64
#define DDIM   128
#define FDIM   512
#define NLAYER 2
#define NTHR   256
#define LNEPS  1e-5f

typedef unsigned long long u64;

struct SMem {
    float xs[TOK][DDIM + 4];
    float qs[TOK][DDIM + 4];
    float ks[TOK][DDIM + 4];
    float vs[TOK][DDIM + 4];
    float cb[TOK][DDIM + 4];
    float ws[3][DDIM][32];     // 3-buffer ring, swizzled 128x32 weight tiles
};

__device__ __forceinline__ void fma2(u64 &d, u64 a, u64 b) {
    asm("fma.rn.f32x2 %0, %1, %2, %0;" : "+l"(d) : "l"(a), "l"(b));
}

__device__ __forceinline__ float pairsum(u64 v) {
    float lo = __uint_as_float((unsigned)(v & 0xffffffffULL));
    float hi = __uint_as_float((unsigned)(v >> 32));
    return lo + hi;
}

__device__ __forceinline__ float gelu_exact(float v) {
    return 0.5f * v * (1.0f + erff(v * 0.70710678118654752f));
}

__device__ __forceinline__ void cp_commit() {
    asm volatile("cp.async.commit_group;" ::: "memory");
}
template <int N>
__device__ __forceinline__ void cp_wait() {
    asm volatile("cp.async.wait_group %0;" :: "n"(N) : "memory");
}

// stage 128 cols x 32 k of weights into swizzled buf via cp.async (16B, 4/thr).
// 16B group gd of row col lands at slot gd ^ (col & 7).
__device__ __forceinline__ void stage_tile(float (*buf)[32],
                                           const float* __restrict__ Wg,
                                           int ldw, int dc, int tid)
{
#pragma unroll
    for (int u = 0; u < 4; u++) {
        int idx = u * NTHR + tid;          // 0..1023
        int col = idx >> 3;
        int gd  = idx & 7;
        int slot = (gd ^ (col & 7)) << 2;
        unsigned sa = (unsigned)__cvta_generic_to_shared(&buf[col][slot]);
        asm volatile("cp.async.cg.shared.global [%0], [%1], 16;"
                     :: "r"(sa), "l"(Wg + (long)col * ldw + dc + (gd << 2)) : "memory");
    }
}

// acc[4][8] += A[64][128] @ Wg^T  (Wg row-major, rows=out cols, ldw stride).
// Ring invariant on entry: chunk0 of Wg staged into ws3[rb], committed, and it
// is the ONLY outstanding cp.async group. On exit (nextW != null): chunk0 of
// nextW staged into ws3[(rb+1)%3], sole outstanding group; rb advanced.
__device__ __forceinline__ void mm_acc(
    const float (*A)[DDIM + 4], const float* __restrict__ Wg, int ldw,
    const float* __restrict__ nextW, int nldw,
    float (*ws3)[DDIM][32], float acc[4][8], int tid, int &rb)
{
    const int ty = tid >> 4;
    const int tx = tid & 15;
    const int sw = tx & 7;

    // stage chunk1 into ring slot rb+1  (pending: ch0, ch1)
    stage_tile(ws3[(rb + 1) % 3], Wg, ldw, 32, tid);
    cp_commit();

    u64 acc2[4][8];
#pragma unroll
    for (int i = 0; i < 4; i++)
#pragma unroll
        for (int j = 0; j < 8; j++) acc2[i][j] = 0ULL;

#pragma unroll
    for (int c = 0; c < 4; c++) {
        if (c < 3 || nextW) cp_wait<1>(); else cp_wait<0>();
        __syncthreads();                       // chunk c visible to all

        const float (*wb)[32] = ws3[(rb + c) % 3];
        const int dc = c * 32;
#pragma unroll
        for (int dd = 0; dd < 32; dd += 4) {
            const int g = dd >> 2;
            ulonglong2 av[4], wv[8];
#pragma unroll
            for (int i = 0; i < 4; i++)
                av[i] = *(const ulonglong2*)&A[ty + 16 * i][dc + dd];
#pragma unroll
            for (int j = 0; j < 8; j++)
                wv[j] = *(const ulonglong2*)&wb[tx + 16 * j][(g ^ sw) << 2];
#pragma unroll
            for (int i = 0; i < 4; i++)
#pragma unroll
                for (int j = 0; j < 8; j++) {
                    fma2(acc2[i][j], av[i].x, wv[j].x);
                    fma2(acc2[i][j], av[i].y, wv[j].y);
                }
        }

        // stage chunk c+2 (or next GEMM's chunk0) into ring slot rb+c+2.
        // Safe: sync above guarantees everyone is done reading that slot.
        if (c < 2) {
            stage_tile(ws3[(rb + c + 2) % 3], Wg, ldw, (c + 2) * 32, tid);
            cp_commit();
        } else if (c == 2 && nextW) {
            stage_tile(ws3[(rb + 4) % 3], nextW, nldw, 0, tid);
            cp_commit();
        }
    }
    rb = (rb + 4) % 3;   // == rb+1: next GEMM's chunk0 slot

#pragma unroll
    for (int i = 0; i < 4; i++)
#pragma unroll
        for (int j = 0; j < 8; j++) acc[i][j] += pairsum(acc2[i][j]);
}

// LayerNorm, 4 lanes per row (64 rows x 4 lanes = 256 threads)
__device__ __forceinline__ void lnorm4(float (*x)[DDIM + 4],
                                       const float* __restrict__ g,
                                       const float* __restrict__ b, int tid)
{
    int row = tid >> 2;
    int c0  = (tid & 3) << 5;
    float4 v[8];
    float s = 0.0f;
#pragma unroll
    for (int i = 0; i < 8; i++) {
        v[i] = *(float4*)&x[row][c0 + i * 4];
        s += v[i].x + v[i].y + v[i].z + v[i].w;
    }
    s += __shfl_xor_sync(0xffffffffu, s, 1);
    s += __shfl_xor_sync(0xffffffffu, s, 2);
    float mu = s * (1.0f / 128.0f);
    float q = 0.0f;
#pragma unroll
    for (int i = 0; i < 8; i++) {
        v[i].x -= mu; v[i].y -= mu; v[i].z -= mu; v[i].w -= mu;
        q += v[i].x * v[i].x + v[i].y * v[i].y + v[i].z * v[i].z + v[i].w * v[i].w;
    }
    q += __shfl_xor_sync(0xffffffffu, q, 1);
    q += __shfl_xor_sync(0xffffffffu, q, 2);
    float inv = rsqrtf(q * (1.0f / 128.0f) + LNEPS);
#pragma unroll
    for (int i = 0; i < 8; i++) {
        int c = c0 + i * 4;
        v[i].x = v[i].x * inv * g[c + 0] + b[c + 0];
        v[i].y = v[i].y * inv * g[c + 1] + b[c + 1];
        v[i].z = v[i].z * inv * g[c + 2] + b[c + 2];
        v[i].w = v[i].w * inv * g[c + 3] + b[c + 3];
        *(float4*)&x[row][c] = v[i];
    }
}

__global__ void __launch_bounds__(NTHR, 1)
epochmixer_kernel(const float* __restrict__ z0, const float* __restrict__ z1,
                  const float* __restrict__ z2, const float* __restrict__ cls,
                  const float* __restrict__ Wqkv, const float* __restrict__ bqkv,
                  const float* __restrict__ Wo,  const float* __restrict__ bo,
                  const float* __restrict__ W1,  const float* __restrict__ b1,
                  const float* __restrict__ W2,  const float* __restrict__ b2,
                  const float* __restrict__ ln1g, const float* __restrict__ ln1b,
                  const float* __restrict__ ln2g, const float* __restrict__ ln2b,
                  float* __restrict__ out)
{
    extern __shared__ char smraw[];
    SMem &sm = *reinterpret_cast<SMem*>(smraw);

    const int tid  = threadIdx.x;
    const int ty   = tid >> 4;
    const int tx   = tid & 15;
    const int seq0 = blockIdx.x * GSEQ;
    int rb = 0;

    // prefetch first Wqkv chunk0 into ring slot 0 while loading tokens
    stage_tile(sm.ws[0], Wqkv, DDIM, 0, tid);
    cp_commit();

    // ---- load tokens: row = g*4+s; s=0 CLS, s=1..3 -> z_{s-1}[seq0+g] ----
#pragma unroll
    for (int u = 0; u < 8; u++) {
        int idx = u * NTHR + tid;
        int row = idx >> 5;
        int c4  = (idx & 31) << 2;
        int g   = row >> 2, s = row & 3;
        float4 v;
        if (s == 0) {
            v = *(const float4*)(cls + c4);
        } else {
            const float* zp = (s == 1) ? z0 : (s == 2) ? z1 : z2;
            v = *(const float4*)(zp + (long)(seq0 + g) * DDIM + c4);
        }
        *(float4*)&sm.xs[row][c4] = v;
    }
    // xs published by first mm_acc's iter-0 barrier

    for (int l = 0; l < NLAYER; l++) {
        const float* Wqkv_l = Wqkv + (long)l * 3 * DDIM * DDIM;
        const float* bqkv_l = bqkv + l * 3 * DDIM;
        const float* Wo_l   = Wo   + (long)l * DDIM * DDIM;
        const float* bo_l   = bo   + l * DDIM;
        const float* W1_l   = W1   + (long)l * FDIM * DDIM;
        const float* b1_l   = b1   + l * FDIM;
        const float* W2_l   = W2   + (long)l * DDIM * FDIM;
        const float* b2_l   = b2   + l * DDIM;

        // ---- QKV projections (chained prefetch Q->K->V->Wo) ----
        for (int p = 0; p < 3; p++) {
            const float* Wg   = Wqkv_l + (long)p * DDIM * DDIM;
            const float* Wnxt = (p < 2) ? Wg + DDIM * DDIM : Wo_l;
            float acc[4][8];
#pragma unroll
            for (int i = 0; i < 4; i++)
#pragma unroll
                for (int j = 0; j < 8; j++) acc[i][j] = 0.0f;
            mm_acc(sm.xs, Wg, DDIM, Wnxt, DDIM, sm.ws, acc, tid, rb);
            float (*dst)[DDIM + 4] = (p == 0) ? sm.qs : (p == 1) ? sm.ks : sm.vs;
            const float* bp = bqkv_l + p * DDIM;
#pragma unroll
            for (int i = 0; i < 4; i++)
#pragma unroll
                for (int j = 0; j < 8; j++) {
                    int row = ty + 16 * i, col = tx + 16 * j;
                    dst[row][col] = acc[i][j] + bp[col];
                }
        }
        __syncthreads();

        // ---- attention: one thread per (local seq, head); S=4, dh=16 ----
        if (tid < 128) {
            int g = tid >> 3, h = tid & 7;
            int r0 = g * 4, co = h * 16;
            float sc[4][4];
#pragma unroll
            for (int i = 0; i < 4; i++)
#pragma unroll
                for (int j = 0; j < 4; j++) {
                    float s = 0.0f;
#pragma unroll
                    for (int e = 0; e < 16; e++)
                        s += sm.qs[r0 + i][co + e] * sm.ks[r0 + j][co + e];
                    sc[i][j] = s * 0.25f;
                }
#pragma unroll
            for (int i = 0; i < 4; i++) {
                float m = sc[i][0];
#pragma unroll
                for (int j = 1; j < 4; j++) m = fmaxf(m, sc[i][j]);
                float den = 0.0f;
#pragma unroll
                for (int j = 0; j < 4; j++) {
                    sc[i][j] = expf(sc[i][j] - m);
                    den += sc[i][j];
                }
                float inv = 1.0f / den;
#pragma unroll
                for (int j = 0; j < 4; j++) sc[i][j] *= inv;
            }
#pragma unroll
            for (int i = 0; i < 4; i++)
#pragma unroll
                for (int e = 0; e < 16; e++) {
                    float o = 0.0f;
#pragma unroll
                    for (int j = 0; j < 4; j++)
                        o += sc[i][j] * sm.vs[r0 + j][co + e];
                    sm.cb[r0 + i][co + e] = o;
                }
        }
        // cb published by Wo mm_acc's iter-0 barrier

        // ---- output projection + residual, LN1 ----
        {
            float acc[4][8];
#pragma unroll
            for (int i = 0; i < 4; i++)
#pragma unroll
                for (int j = 0; j < 8; j++) acc[i][j] = 0.0f;
            mm_acc(sm.cb, Wo_l, DDIM, W1_l, DDIM, sm.ws, acc, tid, rb);
#pragma unroll
            for (int i = 0; i < 4; i++)
#pragma unroll
                for (int j = 0; j < 8; j++) {
                    int row = ty + 16 * i, col = tx + 16 * j;
                    sm.xs[row][col] += acc[i][j] + bo_l[col];
                }
        }
        __syncthreads();
        lnorm4(sm.xs, ln1g + l * DDIM, ln1b + l * DDIM, tid);
        __syncthreads();

        // ---- FFN: 4 chunks of 128 ----
        float facc[4][8];
#pragma unroll
        for (int i = 0; i < 4; i++)
#pragma unroll
            for (int j = 0; j < 8; j++) facc[i][j] = 0.0f;

        for (int fc = 0; fc < 4; fc++) {
            float hacc[4][8];
#pragma unroll
            for (int i = 0; i < 4; i++)
#pragma unroll
                for (int j = 0; j < 8; j++) hacc[i][j] = 0.0f;
            mm_acc(sm.xs, W1_l + (long)fc * 128 * DDIM, DDIM,
                   W2_l + fc * 128, FDIM, sm.ws, hacc, tid, rb);
            const float* b1p = b1_l + fc * 128;
#pragma unroll
            for (int i = 0; i < 4; i++)
#pragma unroll
                for (int j = 0; j < 8; j++) {
                    int row = ty + 16 * i, col = tx + 16 * j;
                    sm.cb[row][col] = gelu_exact(hacc[i][j] + b1p[col]);
                }
            const float* Wnxt;
            if (fc < 3)       Wnxt = W1_l + (long)(fc + 1) * 128 * DDIM;
            else if (l == 0)  Wnxt = Wqkv + (long)3 * DDIM * DDIM;
            else              Wnxt = nullptr;
            mm_acc(sm.cb, W2_l + fc * 128, FDIM, Wnxt, DDIM, sm.ws, facc, tid, rb);
        }
#pragma unroll
        for (int i = 0; i < 4; i++)
#pragma unroll
            for (int j = 0; j < 8; j++) {
                int row = ty + 16 * i, col = tx + 16 * j;
                sm.xs[row][col] += facc[i][j] + b2_l[col];
            }
        __syncthreads();
        lnorm4(sm.xs, ln2g + l * DDIM, ln2b + l * DDIM, tid);
        __syncthreads();
    }

    // ---- write CLS tokens ----
#pragma unroll
    for (int u = 0; u < 2; u++) {
        int idx = u * NTHR + tid;
        int g   = idx >> 5;
        int c4  = (idx & 31) << 2;
        *(float4*)(out + (long)(seq0 + g) * DDIM + c4) = *(float4*)&sm.xs[g * 4][c4];
    }
}

extern "C" void kernel_launch(void* const* d_in, const int* in_sizes, int n_in,
                              void* d_out, int out_size)
{
    (void)in_sizes; (void)n_in; (void)out_size;
    const float* z0   = (const float*)d_in[0];
    const float* z1   = (const float*)d_in[1];
    const float* z2   = (const float*)d_in[2];
    const float* cls  = (const float*)d_in[3];
    const float* Wqkv = (const float*)d_in[4];
    const float* bqkv = (const float*)d_in[5];
    const float* Wo   = (const float*)d_in[6];
    const float* bo   = (const float*)d_in[7];
    const float* W1   = (const float*)d_in[8];
    const float* b1   = (const float*)d_in[9];
    const float* W2   = (const float*)d_in[10];
    const float* b2   = (const float*)d_in[11];
    const float* ln1g = (const float*)d_in[12];
    const float* ln1b = (const float*)d_in[13];
    const float* ln2g = (const float*)d_in[14];
    const float* ln2b = (const float*)d_in[15];
    float* out = (float*)d_out;

    cudaFuncSetAttribute(epochmixer_kernel,
                         cudaFuncAttributeMaxDynamicSharedMemorySize,
                         (int)sizeof(SMem));
    epochmixer_kernel<<<NSEQ / GSEQ, NTHR, sizeof(SMem)>>>(
        z0, z1, z2, cls, Wqkv, bqkv, Wo, bo, W1, b1, W2, b2,
        ln1g, ln1b, ln2g, ln2b, out);
}

// round 9
// speedup vs baseline: 1.7734x; 1.7401x over previous
#include <cuda_runtime.h>
#include <cuda_bf16.h>

// EpochMixer R8: legacy HMMA (mma.sync m16n8k16 bf16) with hi/lo split precision.
// 2048 blocks x 16 seqs (64 tokens). 3-pass split GEMMs (AhWh+AhWl+AlWh),
// 2-pass for FFN2. Weights pre-split by wsplit_kernel into __device__ scratch.

#define NSEQ  32768
#define GSEQ  16
#define NTHR  256
#define NTILE 24
#define LNEPS 1e-5f

// pre-split weights, [slot][hi/lo][n][k] row-major.
// slots per layer: Wq,Wk,Wv,Wo, W1f0,W2f0,W1f1,W2f1,W1f2,W2f2,W1f3,W2f3
__device__ __nv_bfloat16 g_wt[NTILE][2][128][128];

struct SMem {
    float xs[64][132];                 // residual stream (fp32)
    float qs[64][132];
    float ks[64][132];
    float vs[64][132];
    __nv_bfloat16 ax[2][64][136];      // A operand hi/lo
    __nv_bfloat16 cb[64][136];         // gelu-h operand (single bf16)
    __nv_bfloat16 ring[3][2][128][24]; // k16 weight chunks, hi/lo, 3-slot ring
};

__global__ void wsplit_kernel(const float* __restrict__ Wqkv, const float* __restrict__ Wo,
                              const float* __restrict__ W1,   const float* __restrict__ W2) {
    int idx = blockIdx.x * blockDim.x + threadIdx.x;
    if (idx >= NTILE * 16384) return;
    int t = idx >> 14, e = idx & 16383, n = e >> 7, k = e & 127;
    int l = t / 12, tt = t % 12;
    float w;
    if (tt < 3)       w = Wqkv[((l * 3 + tt) * 128 + n) * 128 + k];
    else if (tt == 3) w = Wo[(l * 128 + n) * 128 + k];
    else { int q = tt - 4, fc = q >> 1;
        if (!(q & 1)) w = W1[(l * 512 + fc * 128 + n) * 128 + k];
        else          w = W2[(l * 128 + n) * 512 + fc * 128 + k]; }
    __nv_bfloat16 hi = __float2bfloat16(w);
    g_wt[t][0][n][k] = hi;
    g_wt[t][1][n][k] = __float2bfloat16(w - __bfloat162float(hi));
}

__device__ __forceinline__ unsigned smaddr(const void* p) {
    return (unsigned)__cvta_generic_to_shared(p);
}
__device__ __forceinline__ void ldsm4(unsigned a, unsigned r[4]) {
    asm volatile("ldmatrix.sync.aligned.m8n8.x4.shared.b16 {%0,%1,%2,%3}, [%4];"
                 : "=r"(r[0]), "=r"(r[1]), "=r"(r[2]), "=r"(r[3]) : "r"(a));
}
__device__ __forceinline__ void hmma(float d[4], const unsigned a[4],
                                     unsigned b0, unsigned b1) {
    asm volatile("mma.sync.aligned.m16n8k16.row.col.f32.bf16.bf16.f32 "
                 "{%0,%1,%2,%3},{%4,%5,%6,%7},{%8,%9},{%0,%1,%2,%3};"
                 : "+f"(d[0]), "+f"(d[1]), "+f"(d[2]), "+f"(d[3])
                 : "r"(a[0]), "r"(a[1]), "r"(a[2]), "r"(a[3]), "r"(b0), "r"(b1));
}
__device__ __forceinline__ float gelu_exact(float v) {
    return 0.5f * v * (1.0f + erff(v * 0.70710678118654752f));
}

// stage one k16 chunk (hi+lo, 128 rows x 32B each) into ring slot s3
__device__ __forceinline__ void stage_chunk(SMem* sm, int s3, int slot, int kc, int tid) {
#pragma unroll
    for (int u = 0; u < 2; u++) {
        int idx = u * NTHR + tid;          // 0..511
        int h = idx >> 8, rem = idx & 255, n = rem >> 1, x = rem & 1;
        unsigned dst = smaddr(&sm->ring[s3][h][n][x * 8]);
        const void* src = &g_wt[slot][h][n][kc * 16 + x * 8];
        asm volatile("cp.async.cg.shared.global [%0], [%1], 16;"
                     :: "r"(dst), "l"(src) : "memory");
    }
    asm volatile("cp.async.commit_group;" ::: "memory");
}

// acc[8][4] += A[64][128] @ W(slot)^T.  a_lo==null -> 2-pass.
// Entry invariant: chunk0 of slot staged into ring[rb], sole outstanding group.
// Exit (next_slot>=0): chunk0 of next_slot staged, rb advanced.
__device__ void gemm(SMem* sm, const __nv_bfloat16 (*a_hi)[136],
                     const __nv_bfloat16 (*a_lo)[136],
                     int slot, int next_slot, float acc[8][4], int tid, int& rb)
{
    const int lane = tid & 31, wid = tid >> 5;
    const int mw = (wid & 3) * 16, nh = (wid >> 2) * 64;
    const int arow = mw + (lane & 15), acol = (lane >> 4) * 8;
    const int brow = (lane & 7) + 8 * (lane >> 4), bkoff = ((lane >> 3) & 1) * 8;

#pragma unroll 1
    for (int c = 0; c < 8; c++) {
        if (c < 7)               stage_chunk(sm, (rb + c + 1) % 3, slot, c + 1, tid);
        else if (next_slot >= 0) stage_chunk(sm, (rb + 8) % 3, next_slot, 0, tid);
        if (c < 7 || next_slot >= 0)
            asm volatile("cp.async.wait_group 1;" ::: "memory");
        else
            asm volatile("cp.async.wait_group 0;" ::: "memory");
        __syncthreads();

        const int s3 = (rb + c) % 3;
        unsigned ah[4], al[4];
        ldsm4(smaddr(&a_hi[arow][c * 16 + acol]), ah);
        if (a_lo) ldsm4(smaddr(&a_lo[arow][c * 16 + acol]), al);
#pragma unroll
        for (int jp = 0; jp < 4; jp++) {
            int nr = nh + jp * 16 + brow;
            unsigned wh[4], wl[4];
            ldsm4(smaddr(&sm->ring[s3][0][nr][bkoff]), wh);
            ldsm4(smaddr(&sm->ring[s3][1][nr][bkoff]), wl);
#pragma unroll
            for (int t = 0; t < 2; t++) {
                float* d = acc[jp * 2 + t];
                hmma(d, ah, wh[2 * t], wh[2 * t + 1]);
                hmma(d, ah, wl[2 * t], wl[2 * t + 1]);
                if (a_lo) hmma(d, al, wh[2 * t], wh[2 * t + 1]);
            }
        }
    }
    rb = (rb + 8) % 3;
}

// write acc + bias into fp32 dst (qs/ks/vs)
__device__ __forceinline__ void epi_store(float (*dst)[132], float acc[8][4],
                                          const float* bias, int tid) {
    int lane = tid & 31, wid = tid >> 5;
    int r0 = (wid & 3) * 16 + (lane >> 2), nh = (wid >> 2) * 64, c0 = (lane & 3) * 2;
#pragma unroll
    for (int j = 0; j < 8; j++) {
        int c = nh + 8 * j + c0;
        float b0 = __ldg(bias + c), b1 = __ldg(bias + c + 1);
        dst[r0][c]         = acc[j][0] + b0;
        dst[r0][c + 1]     = acc[j][1] + b1;
        dst[r0 + 8][c]     = acc[j][2] + b0;
        dst[r0 + 8][c + 1] = acc[j][3] + b1;
    }
}
// xs += acc + bias
__device__ __forceinline__ void epi_resid(SMem* sm, float acc[8][4],
                                          const float* bias, int tid) {
    int lane = tid & 31, wid = tid >> 5;
    int r0 = (wid & 3) * 16 + (lane >> 2), nh = (wid >> 2) * 64, c0 = (lane & 3) * 2;
#pragma unroll
    for (int j = 0; j < 8; j++) {
        int c = nh + 8 * j + c0;
        float b0 = __ldg(bias + c), b1 = __ldg(bias + c + 1);
        sm->xs[r0][c]         += acc[j][0] + b0;
        sm->xs[r0][c + 1]     += acc[j][1] + b1;
        sm->xs[r0 + 8][c]     += acc[j][2] + b0;
        sm->xs[r0 + 8][c + 1] += acc[j][3] + b1;
    }
}
// cb = bf16(gelu(acc + b1))
__device__ __forceinline__ void epi_gelu(SMem* sm, float acc[8][4],
                                         const float* bias, int tid) {
    int lane = tid & 31, wid = tid >> 5;
    int r0 = (wid & 3) * 16 + (lane >> 2), nh = (wid >> 2) * 64, c0 = (lane & 3) * 2;
#pragma unroll
    for (int j = 0; j < 8; j++) {
        int c = nh + 8 * j + c0;
        float b0 = __ldg(bias + c), b1 = __ldg(bias + c + 1);
        __nv_bfloat162 p0, p1;
        p0.x = __float2bfloat16(gelu_exact(acc[j][0] + b0));
        p0.y = __float2bfloat16(gelu_exact(acc[j][1] + b1));
        p1.x = __float2bfloat16(gelu_exact(acc[j][2] + b0));
        p1.y = __float2bfloat16(gelu_exact(acc[j][3] + b1));
        *(__nv_bfloat162*)&sm->cb[r0][c]     = p0;
        *(__nv_bfloat162*)&sm->cb[r0 + 8][c] = p1;
    }
}

__device__ __forceinline__ void st_hilo(SMem* sm, int r, int c, float a, float b) {
    __nv_bfloat16 h0 = __float2bfloat16(a), h1 = __float2bfloat16(b);
    __nv_bfloat162 ph, pl;
    ph.x = h0; ph.y = h1;
    pl.x = __float2bfloat16(a - __bfloat162float(h0));
    pl.y = __float2bfloat16(b - __bfloat162float(h1));
    *(__nv_bfloat162*)&sm->ax[0][r][c] = ph;
    *(__nv_bfloat162*)&sm->ax[1][r][c] = pl;
}

// LayerNorm rows of xs (4 lanes/row), write xs AND ax hi/lo
__device__ void lnorm_conv(SMem* sm, const float* g, const float* b, int tid) {
    int row = tid >> 2, c0 = (tid & 3) << 5;
    float v[32];
    float s = 0.f;
#pragma unroll
    for (int i = 0; i < 8; i++) {
        float4 f = *(float4*)&sm->xs[row][c0 + i * 4];
        v[i*4] = f.x; v[i*4+1] = f.y; v[i*4+2] = f.z; v[i*4+3] = f.w;
        s += f.x + f.y + f.z + f.w;
    }
    s += __shfl_xor_sync(0xffffffffu, s, 1);
    s += __shfl_xor_sync(0xffffffffu, s, 2);
    float mu = s * (1.f / 128.f);
    float q = 0.f;
#pragma unroll
    for (int j = 0; j < 32; j++) { v[j] -= mu; q += v[j] * v[j]; }
    q += __shfl_xor_sync(0xffffffffu, q, 1);
    q += __shfl_xor_sync(0xffffffffu, q, 2);
    float inv = rsqrtf(q * (1.f / 128.f) + LNEPS);
#pragma unroll
    for (int j = 0; j < 32; j += 2) {
        int c = c0 + j;
        float y0 = v[j]   * inv * __ldg(g + c)     + __ldg(b + c);
        float y1 = v[j+1] * inv * __ldg(g + c + 1) + __ldg(b + c + 1);
        sm->xs[row][c] = y0; sm->xs[row][c + 1] = y1;
        st_hilo(sm, row, c, y0, y1);
    }
}

__device__ void conv_ax(SMem* sm, int tid) {
    int row = tid >> 2, c0 = (tid & 3) << 5;
#pragma unroll
    for (int j = 0; j < 32; j += 2)
        st_hilo(sm, row, c0 + j, sm->xs[row][c0 + j], sm->xs[row][c0 + j + 1]);
}

#define ZACC(A) do { _Pragma("unroll") for (int _i = 0; _i < 8; _i++) \
    { (A)[_i][0]=0.f;(A)[_i][1]=0.f;(A)[_i][2]=0.f;(A)[_i][3]=0.f; } } while (0)

__global__ void __launch_bounds__(NTHR, 1)
mixer_kernel(const float* __restrict__ z0, const float* __restrict__ z1,
             const float* __restrict__ z2, const float* __restrict__ cls,
             const float* __restrict__ bqkv, const float* __restrict__ bo,
             const float* __restrict__ b1,  const float* __restrict__ b2,
             const float* __restrict__ ln1g, const float* __restrict__ ln1b,
             const float* __restrict__ ln2g, const float* __restrict__ ln2b,
             float* __restrict__ out)
{
    extern __shared__ char smraw[];
    SMem* sm = (SMem*)smraw;
    const int tid = threadIdx.x;
    const int seq0 = blockIdx.x * GSEQ;
    int rb = 0;

    stage_chunk(sm, 0, 0, 0, tid);   // layer-0 Wq chunk0

    // tokens -> xs: row 4g+s; s=0 CLS else z_{s-1}[seq0+g]
#pragma unroll
    for (int u = 0; u < 8; u++) {
        int idx = u * NTHR + tid, row = idx >> 5, c4 = (idx & 31) << 2;
        int g = row >> 2, s = row & 3;
        float4 v;
        if (s == 0) v = *(const float4*)(cls + c4);
        else {
            const float* zp = (s == 1) ? z0 : (s == 2) ? z1 : z2;
            v = *(const float4*)(zp + (long)(seq0 + g) * 128 + c4);
        }
        *(float4*)&sm->xs[row][c4] = v;
    }
    __syncthreads();
    conv_ax(sm, tid);

    float acc[8][4], facc[8][4];

    for (int l = 0; l < 2; l++) {
        int sb = 12 * l;
        // ---- QKV ----
        ZACC(acc); gemm(sm, sm->ax[0], sm->ax[1], sb + 0, sb + 1, acc, tid, rb);
        epi_store(sm->qs, acc, bqkv + l * 384, tid);
        ZACC(acc); gemm(sm, sm->ax[0], sm->ax[1], sb + 1, sb + 2, acc, tid, rb);
        epi_store(sm->ks, acc, bqkv + l * 384 + 128, tid);
        ZACC(acc); gemm(sm, sm->ax[0], sm->ax[1], sb + 2, sb + 3, acc, tid, rb);
        epi_store(sm->vs, acc, bqkv + l * 384 + 256, tid);
        __syncthreads();

        // ---- attention: one thread per (seq, head); writes ax hi/lo ----
        if (tid < 128) {
            int g = tid >> 3, h = tid & 7;
            int r0 = g * 4, co = h * 16;
            float sc[4][4];
#pragma unroll
            for (int i = 0; i < 4; i++)
#pragma unroll
                for (int j = 0; j < 4; j++) {
                    float s = 0.f;
#pragma unroll
                    for (int e = 0; e < 16; e++)
                        s += sm->qs[r0 + i][co + e] * sm->ks[r0 + j][co + e];
                    sc[i][j] = s * 0.25f;
                }
#pragma unroll
            for (int i = 0; i < 4; i++) {
                float m = fmaxf(fmaxf(sc[i][0], sc[i][1]), fmaxf(sc[i][2], sc[i][3]));
                float den = 0.f;
#pragma unroll
                for (int j = 0; j < 4; j++) { sc[i][j] = expf(sc[i][j] - m); den += sc[i][j]; }
                float inv = 1.f / den;
#pragma unroll
                for (int j = 0; j < 4; j++) sc[i][j] *= inv;
            }
#pragma unroll
            for (int i = 0; i < 4; i++)
#pragma unroll
                for (int e = 0; e < 16; e += 2) {
                    float o0 = 0.f, o1 = 0.f;
#pragma unroll
                    for (int j = 0; j < 4; j++) {
                        o0 += sc[i][j] * sm->vs[r0 + j][co + e];
                        o1 += sc[i][j] * sm->vs[r0 + j][co + e + 1];
                    }
                    st_hilo(sm, r0 + i, co + e, o0, o1);
                }
        }
        // ax published by Wo gemm's chunk-0 barrier

        // ---- Wo + residual + LN1 ----
        ZACC(acc); gemm(sm, sm->ax[0], sm->ax[1], sb + 3, sb + 4, acc, tid, rb);
        epi_resid(sm, acc, bo + l * 128, tid);
        __syncthreads();
        lnorm_conv(sm, ln1g + l * 128, ln1b + l * 128, tid);

        // ---- FFN ----
        ZACC(facc);
        for (int fc = 0; fc < 4; fc++) {
            ZACC(acc);
            gemm(sm, sm->ax[0], sm->ax[1], sb + 4 + 2 * fc, sb + 5 + 2 * fc, acc, tid, rb);
            epi_gelu(sm, acc, b1 + l * 512 + fc * 128, tid);
            int nxt = (fc < 3) ? sb + 6 + 2 * fc : (l == 0 ? 12 : -1);
            gemm(sm, sm->cb, nullptr, sb + 5 + 2 * fc, nxt, facc, tid, rb);
        }
        epi_resid(sm, facc, b2 + l * 128, tid);
        __syncthreads();
        lnorm_conv(sm, ln2g + l * 128, ln2b + l * 128, tid);
        __syncthreads();
    }

    // CLS rows 4g -> out
#pragma unroll
    for (int u = 0; u < 2; u++) {
        int idx = u * NTHR + tid, g = idx >> 5, c4 = (idx & 31) << 2;
        *(float4*)(out + (long)(seq0 + g) * 128 + c4) = *(float4*)&sm->xs[4 * g][c4];
    }
}

extern "C" void kernel_launch(void* const* d_in, const int* in_sizes, int n_in,
                              void* d_out, int out_size)
{
    (void)in_sizes; (void)n_in; (void)out_size;
    const float* z0   = (const float*)d_in[0];
    const float* z1   = (const float*)d_in[1];
    const float* z2   = (const float*)d_in[2];
    const float* cls  = (const float*)d_in[3];
    const float* Wqkv = (const float*)d_in[4];
    const float* bqkv = (const float*)d_in[5];
    const float* Wo   = (const float*)d_in[6];
    const float* bo   = (const float*)d_in[7];
    const float* W1   = (const float*)d_in[8];
    const float* b1   = (const float*)d_in[9];
    const float* W2   = (const float*)d_in[10];
    const float* b2   = (const float*)d_in[11];
    const float* ln1g = (const float*)d_in[12];
    const float* ln1b = (const float*)d_in[13];
    const float* ln2g = (const float*)d_in[14];
    const float* ln2b = (const float*)d_in[15];
    float* out = (float*)d_out;

    wsplit_kernel<<<(NTILE * 16384 + 255) / 256, 256>>>(Wqkv, Wo, W1, W2);

    cudaFuncSetAttribute(mixer_kernel,
                         cudaFuncAttributeMaxDynamicSharedMemorySize, (int)sizeof(SMem));
    mixer_kernel<<<NSEQ / GSEQ, NTHR, sizeof(SMem)>>>(
        z0, z1, z2, cls, bqkv, bo, b1, b2, ln1g, ln1b, ln2g, ln2b, out);
}

// round 10
// speedup vs baseline: 1.8655x; 1.0519x over previous
#include <cuda_runtime.h>
#include <cuda_bf16.h>

// EpochMixer R9: HMMA bf16 hi/lo split, 512 threads / 16 warps (m16xn32 per warp).

#define NSEQ  32768
#define GSEQ  16
#define NTHR  512
#define NTILE 24
#define LNEPS 1e-5f

// pre-split weights, [slot][hi/lo][n][k] row-major.
// slots per layer: Wq,Wk,Wv,Wo, W1f0,W2f0,W1f1,W2f1,W1f2,W2f2,W1f3,W2f3
__device__ __nv_bfloat16 g_wt[NTILE][2][128][128];

struct SMem {
    float xs[64][132];                 // residual stream (fp32)
    float qs[64][132];
    float ks[64][132];
    float vs[64][132];
    __nv_bfloat16 ax[2][64][136];      // A operand hi/lo
    __nv_bfloat16 cb[64][136];         // gelu-h operand (single bf16)
    __nv_bfloat16 ring[3][2][128][24]; // k16 weight chunks, hi/lo, 3-slot ring
};

__global__ void wsplit_kernel(const float* __restrict__ Wqkv, const float* __restrict__ Wo,
                              const float* __restrict__ W1,   const float* __restrict__ W2) {
    int idx = blockIdx.x * blockDim.x + threadIdx.x;
    if (idx >= NTILE * 16384) return;
    int t = idx >> 14, e = idx & 16383, n = e >> 7, k = e & 127;
    int l = t / 12, tt = t % 12;
    float w;
    if (tt < 3)       w = Wqkv[((l * 3 + tt) * 128 + n) * 128 + k];
    else if (tt == 3) w = Wo[(l * 128 + n) * 128 + k];
    else { int q = tt - 4, fc = q >> 1;
        if (!(q & 1)) w = W1[(l * 512 + fc * 128 + n) * 128 + k];
        else          w = W2[(l * 128 + n) * 512 + fc * 128 + k]; }
    __nv_bfloat16 hi = __float2bfloat16(w);
    g_wt[t][0][n][k] = hi;
    g_wt[t][1][n][k] = __float2bfloat16(w - __bfloat162float(hi));
}

__device__ __forceinline__ unsigned smaddr(const void* p) {
    return (unsigned)__cvta_generic_to_shared(p);
}
__device__ __forceinline__ void ldsm4(unsigned a, unsigned r[4]) {
    asm volatile("ldmatrix.sync.aligned.m8n8.x4.shared.b16 {%0,%1,%2,%3}, [%4];"
                 : "=r"(r[0]), "=r"(r[1]), "=r"(r[2]), "=r"(r[3]) : "r"(a));
}
__device__ __forceinline__ void hmma(float d[4], const unsigned a[4],
                                     unsigned b0, unsigned b1) {
    asm volatile("mma.sync.aligned.m16n8k16.row.col.f32.bf16.bf16.f32 "
                 "{%0,%1,%2,%3},{%4,%5,%6,%7},{%8,%9},{%0,%1,%2,%3};"
                 : "+f"(d[0]), "+f"(d[1]), "+f"(d[2]), "+f"(d[3])
                 : "r"(a[0]), "r"(a[1]), "r"(a[2]), "r"(a[3]), "r"(b0), "r"(b1));
}
__device__ __forceinline__ float gelu_exact(float v) {
    return 0.5f * v * (1.0f + erff(v * 0.70710678118654752f));
}

// stage one k16 chunk (hi+lo, 128 rows x 32B each = 512 x 16B) into ring slot s3
__device__ __forceinline__ void stage_chunk(SMem* sm, int s3, int slot, int kc, int tid) {
    int h = tid >> 8, rem = tid & 255, n = rem >> 1, x = rem & 1;
    unsigned dst = smaddr(&sm->ring[s3][h][n][x * 8]);
    const void* src = &g_wt[slot][h][n][kc * 16 + x * 8];
    asm volatile("cp.async.cg.shared.global [%0], [%1], 16;"
                 :: "r"(dst), "l"(src) : "memory");
    asm volatile("cp.async.commit_group;" ::: "memory");
}

// acc[4][4] += A[64][128] @ W(slot)^T (this warp's m16 x n32 slice).
// a_lo==null -> 2-pass. Entry: chunk0 of slot staged into ring[rb], sole group.
// Exit (next_slot>=0): chunk0 of next_slot staged, rb advanced.
__device__ void gemm(SMem* sm, const __nv_bfloat16 (*a_hi)[136],
                     const __nv_bfloat16 (*a_lo)[136],
                     int slot, int next_slot, float acc[4][4], int tid, int& rb)
{
    const int lane = tid & 31, wid = tid >> 5;
    const int mw = (wid & 3) * 16, nh = (wid >> 2) * 32;
    const int arow = mw + (lane & 15), acol = (lane >> 4) * 8;
    const int brow = (lane & 7) + 8 * (lane >> 4), bkoff = ((lane >> 3) & 1) * 8;

#pragma unroll 1
    for (int c = 0; c < 8; c++) {
        if (c < 7)               stage_chunk(sm, (rb + c + 1) % 3, slot, c + 1, tid);
        else if (next_slot >= 0) stage_chunk(sm, (rb + 8) % 3, next_slot, 0, tid);
        if (c < 7 || next_slot >= 0)
            asm volatile("cp.async.wait_group 1;" ::: "memory");
        else
            asm volatile("cp.async.wait_group 0;" ::: "memory");
        __syncthreads();

        const int s3 = (rb + c) % 3;
        unsigned ah[4], al[4];
        ldsm4(smaddr(&a_hi[arow][c * 16 + acol]), ah);
        if (a_lo) ldsm4(smaddr(&a_lo[arow][c * 16 + acol]), al);
#pragma unroll
        for (int jp = 0; jp < 2; jp++) {
            int nr = nh + jp * 16 + brow;
            unsigned wh[4], wl[4];
            ldsm4(smaddr(&sm->ring[s3][0][nr][bkoff]), wh);
            ldsm4(smaddr(&sm->ring[s3][1][nr][bkoff]), wl);
#pragma unroll
            for (int t = 0; t < 2; t++) {
                float* d = acc[jp * 2 + t];
                hmma(d, ah, wh[2 * t], wh[2 * t + 1]);
                hmma(d, ah, wl[2 * t], wl[2 * t + 1]);
                if (a_lo) hmma(d, al, wh[2 * t], wh[2 * t + 1]);
            }
        }
    }
    rb = (rb + 8) % 3;
}

// write acc + bias into fp32 dst (qs/ks/vs)
__device__ __forceinline__ void epi_store(float (*dst)[132], float acc[4][4],
                                          const float* bias, int tid) {
    int lane = tid & 31, wid = tid >> 5;
    int r0 = (wid & 3) * 16 + (lane >> 2), nh = (wid >> 2) * 32, c0 = (lane & 3) * 2;
#pragma unroll
    for (int j = 0; j < 4; j++) {
        int c = nh + 8 * j + c0;
        float b0 = __ldg(bias + c), b1 = __ldg(bias + c + 1);
        dst[r0][c]         = acc[j][0] + b0;
        dst[r0][c + 1]     = acc[j][1] + b1;
        dst[r0 + 8][c]     = acc[j][2] + b0;
        dst[r0 + 8][c + 1] = acc[j][3] + b1;
    }
}
// xs += acc + bias
__device__ __forceinline__ void epi_resid(SMem* sm, float acc[4][4],
                                          const float* bias, int tid) {
    int lane = tid & 31, wid = tid >> 5;
    int r0 = (wid & 3) * 16 + (lane >> 2), nh = (wid >> 2) * 32, c0 = (lane & 3) * 2;
#pragma unroll
    for (int j = 0; j < 4; j++) {
        int c = nh + 8 * j + c0;
        float b0 = __ldg(bias + c), b1 = __ldg(bias + c + 1);
        sm->xs[r0][c]         += acc[j][0] + b0;
        sm->xs[r0][c + 1]     += acc[j][1] + b1;
        sm->xs[r0 + 8][c]     += acc[j][2] + b0;
        sm->xs[r0 + 8][c + 1] += acc[j][3] + b1;
    }
}
// cb = bf16(gelu(acc + b1))
__device__ __forceinline__ void epi_gelu(SMem* sm, float acc[4][4],
                                         const float* bias, int tid) {
    int lane = tid & 31, wid = tid >> 5;
    int r0 = (wid & 3) * 16 + (lane >> 2), nh = (wid >> 2) * 32, c0 = (lane & 3) * 2;
#pragma unroll
    for (int j = 0; j < 4; j++) {
        int c = nh + 8 * j + c0;
        float b0 = __ldg(bias + c), b1 = __ldg(bias + c + 1);
        __nv_bfloat162 p0, p1;
        p0.x = __float2bfloat16(gelu_exact(acc[j][0] + b0));
        p0.y = __float2bfloat16(gelu_exact(acc[j][1] + b1));
        p1.x = __float2bfloat16(gelu_exact(acc[j][2] + b0));
        p1.y = __float2bfloat16(gelu_exact(acc[j][3] + b1));
        *(__nv_bfloat162*)&sm->cb[r0][c]     = p0;
        *(__nv_bfloat162*)&sm->cb[r0 + 8][c] = p1;
    }
}

__device__ __forceinline__ void st_hilo(SMem* sm, int r, int c, float a, float b) {
    __nv_bfloat16 h0 = __float2bfloat16(a), h1 = __float2bfloat16(b);
    __nv_bfloat162 ph, pl;
    ph.x = h0; ph.y = h1;
    pl.x = __float2bfloat16(a - __bfloat162float(h0));
    pl.y = __float2bfloat16(b - __bfloat162float(h1));
    *(__nv_bfloat162*)&sm->ax[0][r][c] = ph;
    *(__nv_bfloat162*)&sm->ax[1][r][c] = pl;
}

// LayerNorm rows of xs (8 lanes/row), write xs AND ax hi/lo
__device__ void lnorm_conv(SMem* sm, const float* g, const float* b, int tid) {
    int row = tid >> 3, c0 = (tid & 7) << 4;
    float v[16];
    float s = 0.f;
#pragma unroll
    for (int i = 0; i < 4; i++) {
        float4 f = *(float4*)&sm->xs[row][c0 + i * 4];
        v[i*4] = f.x; v[i*4+1] = f.y; v[i*4+2] = f.z; v[i*4+3] = f.w;
        s += f.x + f.y + f.z + f.w;
    }
    s += __shfl_xor_sync(0xffffffffu, s, 1);
    s += __shfl_xor_sync(0xffffffffu, s, 2);
    s += __shfl_xor_sync(0xffffffffu, s, 4);
    float mu = s * (1.f / 128.f);
    float q = 0.f;
#pragma unroll
    for (int j = 0; j < 16; j++) { v[j] -= mu; q += v[j] * v[j]; }
    q += __shfl_xor_sync(0xffffffffu, q, 1);
    q += __shfl_xor_sync(0xffffffffu, q, 2);
    q += __shfl_xor_sync(0xffffffffu, q, 4);
    float inv = rsqrtf(q * (1.f / 128.f) + LNEPS);
#pragma unroll
    for (int j = 0; j < 16; j += 2) {
        int c = c0 + j;
        float y0 = v[j]   * inv * __ldg(g + c)     + __ldg(b + c);
        float y1 = v[j+1] * inv * __ldg(g + c + 1) + __ldg(b + c + 1);
        sm->xs[row][c] = y0; sm->xs[row][c + 1] = y1;
        st_hilo(sm, row, c, y0, y1);
    }
}

__device__ void conv_ax(SMem* sm, int tid) {
    int row = tid >> 3, c0 = (tid & 7) << 4;
#pragma unroll
    for (int j = 0; j < 16; j += 2)
        st_hilo(sm, row, c0 + j, sm->xs[row][c0 + j], sm->xs[row][c0 + j + 1]);
}

#define ZACC(A) do { _Pragma("unroll") for (int _i = 0; _i < 4; _i++) \
    { (A)[_i][0]=0.f;(A)[_i][1]=0.f;(A)[_i][2]=0.f;(A)[_i][3]=0.f; } } while (0)

__global__ void __launch_bounds__(NTHR, 1)
mixer_kernel(const float* __restrict__ z0, const float* __restrict__ z1,
             const float* __restrict__ z2, const float* __restrict__ cls,
             const float* __restrict__ bqkv, const float* __restrict__ bo,
             const float* __restrict__ b1,  const float* __restrict__ b2,
             const float* __restrict__ ln1g, const float* __restrict__ ln1b,
             const float* __restrict__ ln2g, const float* __restrict__ ln2b,
             float* __restrict__ out)
{
    extern __shared__ char smraw[];
    SMem* sm = (SMem*)smraw;
    const int tid = threadIdx.x;
    const int seq0 = blockIdx.x * GSEQ;
    int rb = 0;

    stage_chunk(sm, 0, 0, 0, tid);   // layer-0 Wq chunk0

    // tokens -> xs: row 4g+s; s=0 CLS else z_{s-1}[seq0+g]
#pragma unroll
    for (int u = 0; u < 4; u++) {
        int idx = u * NTHR + tid, row = idx >> 5, c4 = (idx & 31) << 2;
        int g = row >> 2, s = row & 3;
        float4 v;
        if (s == 0) v = *(const float4*)(cls + c4);
        else {
            const float* zp = (s == 1) ? z0 : (s == 2) ? z1 : z2;
            v = *(const float4*)(zp + (long)(seq0 + g) * 128 + c4);
        }
        *(float4*)&sm->xs[row][c4] = v;
    }
    __syncthreads();
    conv_ax(sm, tid);

    float acc[4][4], facc[4][4];

    for (int l = 0; l < 2; l++) {
        int sb = 12 * l;
        // ---- QKV ----
        ZACC(acc); gemm(sm, sm->ax[0], sm->ax[1], sb + 0, sb + 1, acc, tid, rb);
        epi_store(sm->qs, acc, bqkv + l * 384, tid);
        ZACC(acc); gemm(sm, sm->ax[0], sm->ax[1], sb + 1, sb + 2, acc, tid, rb);
        epi_store(sm->ks, acc, bqkv + l * 384 + 128, tid);
        ZACC(acc); gemm(sm, sm->ax[0], sm->ax[1], sb + 2, sb + 3, acc, tid, rb);
        epi_store(sm->vs, acc, bqkv + l * 384 + 256, tid);
        __syncthreads();

        // ---- attention: one thread per (seq, head); writes ax hi/lo ----
        if (tid < 128) {
            int g = tid >> 3, h = tid & 7;
            int r0 = g * 4, co = h * 16;
            float sc[4][4];
#pragma unroll
            for (int i = 0; i < 4; i++)
#pragma unroll
                for (int j = 0; j < 4; j++) {
                    float s = 0.f;
#pragma unroll
                    for (int e = 0; e < 16; e++)
                        s += sm->qs[r0 + i][co + e] * sm->ks[r0 + j][co + e];
                    sc[i][j] = s * 0.25f;
                }
#pragma unroll
            for (int i = 0; i < 4; i++) {
                float m = fmaxf(fmaxf(sc[i][0], sc[i][1]), fmaxf(sc[i][2], sc[i][3]));
                float den = 0.f;
#pragma unroll
                for (int j = 0; j < 4; j++) { sc[i][j] = expf(sc[i][j] - m); den += sc[i][j]; }
                float inv = 1.f / den;
#pragma unroll
                for (int j = 0; j < 4; j++) sc[i][j] *= inv;
            }
#pragma unroll
            for (int i = 0; i < 4; i++)
#pragma unroll
                for (int e = 0; e < 16; e += 2) {
                    float o0 = 0.f, o1 = 0.f;
#pragma unroll
                    for (int j = 0; j < 4; j++) {
                        o0 += sc[i][j] * sm->vs[r0 + j][co + e];
                        o1 += sc[i][j] * sm->vs[r0 + j][co + e + 1];
                    }
                    st_hilo(sm, r0 + i, co + e, o0, o1);
                }
        }
        // ax published by Wo gemm's chunk-0 barrier

        // ---- Wo + residual + LN1 ----
        ZACC(acc); gemm(sm, sm->ax[0], sm->ax[1], sb + 3, sb + 4, acc, tid, rb);
        epi_resid(sm, acc, bo + l * 128, tid);
        __syncthreads();
        lnorm_conv(sm, ln1g + l * 128, ln1b + l * 128, tid);

        // ---- FFN ----
        ZACC(facc);
        for (int fc = 0; fc < 4; fc++) {
            ZACC(acc);
            gemm(sm, sm->ax[0], sm->ax[1], sb + 4 + 2 * fc, sb + 5 + 2 * fc, acc, tid, rb);
            epi_gelu(sm, acc, b1 + l * 512 + fc * 128, tid);
            int nxt = (fc < 3) ? sb + 6 + 2 * fc : (l == 0 ? 12 : -1);
            gemm(sm, sm->cb, nullptr, sb + 5 + 2 * fc, nxt, facc, tid, rb);
        }
        epi_resid(sm, facc, b2 + l * 128, tid);
        __syncthreads();
        lnorm_conv(sm, ln2g + l * 128, ln2b + l * 128, tid);
        __syncthreads();
    }

    // CLS rows 4g -> out: 512 threads, one float4 each
    {
        int g = tid >> 5, c4 = (tid & 31) << 2;
        *(float4*)(out + (long)(seq0 + g) * 128 + c4) = *(float4*)&sm->xs[4 * g][c4];
    }
}

extern "C" void kernel_launch(void* const* d_in, const int* in_sizes, int n_in,
                              void* d_out, int out_size)
{
    (void)in_sizes; (void)n_in; (void)out_size;
    const float* z0   = (const float*)d_in[0];
    const float* z1   = (const float*)d_in[1];
    const float* z2   = (const float*)d_in[2];
    const float* cls  = (const float*)d_in[3];
    const float* Wqkv = (const float*)d_in[4];
    const float* bqkv = (const float*)d_in[5];
    const float* Wo   = (const float*)d_in[6];
    const float* bo   = (const float*)d_in[7];
    const float* W1   = (const float*)d_in[8];
    const float* b1   = (const float*)d_in[9];
    const float* W2   = (const float*)d_in[10];
    const float* b2   = (const float*)d_in[11];
    const float* ln1g = (const float*)d_in[12];
    const float* ln1b = (const float*)d_in[13];
    const float* ln2g = (const float*)d_in[14];
    const float* ln2b = (const float*)d_in[15];
    float* out = (float*)d_out;

    wsplit_kernel<<<(NTILE * 16384 + 383) / 384, 384>>>(Wqkv, Wo, W1, W2);

    cudaFuncSetAttribute(mixer_kernel,
                         cudaFuncAttributeMaxDynamicSharedMemorySize, (int)sizeof(SMem));
    mixer_kernel<<<NSEQ / GSEQ, NTHR, sizeof(SMem)>>>(
        z0, z1, z2, cls, bqkv, bo, b1, b2, ln1g, ln1b, ln2g, ln2b, out);
}

// round 14
// speedup vs baseline: 1.9981x; 1.0711x over previous
#include <cuda_runtime.h>
#include <cuda_bf16.h>

// EpochMixer R13: HMMA bf16 hi/lo split, 512 threads / 16 warps (m16xn32/warp),
// k32 chunks per barrier (96 syncs/block), 2-slot ring (80B row stride,
// 16B-aligned + ldsm conflict-free), stage-after-sync.

#define NSEQ  32768
#define GSEQ  16
#define NTHR  512
#define NTILE 24
#define LNEPS 1e-5f

// pre-split weights, [slot][hi/lo][n][k] row-major.
// slots per layer: Wq,Wk,Wv,Wo, W1f0,W2f0,W1f1,W2f1,W1f2,W2f2,W1f3,W2f3
__device__ __nv_bfloat16 g_wt[NTILE][2][128][128];

struct SMem {
    float xs[64][132];                 // residual stream (fp32)
    float qs[64][132];
    float ks[64][132];
    float vs[64][132];
    __nv_bfloat16 ax[2][64][136];      // A operand hi/lo
    __nv_bfloat16 cb[64][136];         // gelu-h operand (single bf16)
    __nv_bfloat16 ring[2][2][128][40]; // k32 weight chunks, hi/lo, 2-slot ring (80B rows)
};

__global__ void wsplit_kernel(const float* __restrict__ Wqkv, const float* __restrict__ Wo,
                              const float* __restrict__ W1,   const float* __restrict__ W2) {
    int idx = blockIdx.x * blockDim.x + threadIdx.x;
    if (idx >= NTILE * 16384) return;
    int t = idx >> 14, e = idx & 16383, n = e >> 7, k = e & 127;
    int l = t / 12, tt = t % 12;
    float w;
    if (tt < 3)       w = Wqkv[((l * 3 + tt) * 128 + n) * 128 + k];
    else if (tt == 3) w = Wo[(l * 128 + n) * 128 + k];
    else { int q = tt - 4, fc = q >> 1;
        if (!(q & 1)) w = W1[(l * 512 + fc * 128 + n) * 128 + k];
        else          w = W2[(l * 128 + n) * 512 + fc * 128 + k]; }
    __nv_bfloat16 hi = __float2bfloat16(w);
    g_wt[t][0][n][k] = hi;
    g_wt[t][1][n][k] = __float2bfloat16(w - __bfloat162float(hi));
}

__device__ __forceinline__ unsigned smaddr(const void* p) {
    return (unsigned)__cvta_generic_to_shared(p);
}
__device__ __forceinline__ void ldsm4(unsigned a, unsigned r[4]) {
    asm volatile("ldmatrix.sync.aligned.m8n8.x4.shared.b16 {%0,%1,%2,%3}, [%4];"
                 : "=r"(r[0]), "=r"(r[1]), "=r"(r[2]), "=r"(r[3]) : "r"(a));
}
__device__ __forceinline__ void hmma(float d[4], const unsigned a[4],
                                     unsigned b0, unsigned b1) {
    asm volatile("mma.sync.aligned.m16n8k16.row.col.f32.bf16.bf16.f32 "
                 "{%0,%1,%2,%3},{%4,%5,%6,%7},{%8,%9},{%0,%1,%2,%3};"
                 : "+f"(d[0]), "+f"(d[1]), "+f"(d[2]), "+f"(d[3])
                 : "r"(a[0]), "r"(a[1]), "r"(a[2]), "r"(a[3]), "r"(b0), "r"(b1));
}
__device__ __forceinline__ float gelu_exact(float v) {
    return 0.5f * v * (1.0f + erff(v * 0.70710678118654752f));
}

// stage one k32 chunk (hi+lo, 128 rows x 64B = 1024 x 16B) into ring slot s2
__device__ __forceinline__ void stage_chunk(SMem* sm, int s2, int slot, int kc32, int tid) {
#pragma unroll
    for (int u = 0; u < 2; u++) {
        int idx = u * NTHR + tid;          // 0..1023
        int h = idx >> 9, rem = idx & 511, n = rem >> 2, x = rem & 3;
        unsigned dst = smaddr(&sm->ring[s2][h][n][x * 8]);
        const void* src = &g_wt[slot][h][n][kc32 * 32 + x * 8];
        asm volatile("cp.async.cg.shared.global [%0], [%1], 16;"
                     :: "r"(dst), "l"(src) : "memory");
    }
    asm volatile("cp.async.commit_group;" ::: "memory");
}

// acc[4][4] += A[64][128] @ W(slot)^T (this warp's m16 x n32 slice).
// a_lo==null -> 2-pass. Entry invariant: chunk0 (k32) of slot staged into ring
// slot 0, sole outstanding group. Exit (next_slot>=0): its chunk0 in slot 0.
__device__ void gemm(SMem* sm, const __nv_bfloat16 (*a_hi)[136],
                     const __nv_bfloat16 (*a_lo)[136],
                     int slot, int next_slot, float acc[4][4], int tid)
{
    const int lane = tid & 31, wid = tid >> 5;
    const int mw = (wid & 3) * 16, nh = (wid >> 2) * 32;
    const int arow = mw + (lane & 15), acol = (lane >> 4) * 8;
    const int brow = (lane & 7) + 8 * (lane >> 4), bkoff = ((lane >> 3) & 1) * 8;

#pragma unroll 1
    for (int c = 0; c < 4; c++) {
        asm volatile("cp.async.wait_group 0;" ::: "memory");
        __syncthreads();
        if (c < 3)               stage_chunk(sm, (c + 1) & 1, slot, c + 1, tid);
        else if (next_slot >= 0) stage_chunk(sm, 0, next_slot, 0, tid);

        const int cs = c & 1;
#pragma unroll
        for (int s = 0; s < 2; s++) {
            const int kc = c * 32 + s * 16, ko = s * 16 + bkoff;
            unsigned ah[4], al[4];
            ldsm4(smaddr(&a_hi[arow][kc + acol]), ah);
            if (a_lo) ldsm4(smaddr(&a_lo[arow][kc + acol]), al);
#pragma unroll
            for (int jp = 0; jp < 2; jp++) {
                int nr = nh + jp * 16 + brow;
                unsigned wh[4], wl[4];
                ldsm4(smaddr(&sm->ring[cs][0][nr][ko]), wh);
                ldsm4(smaddr(&sm->ring[cs][1][nr][ko]), wl);
#pragma unroll
                for (int t = 0; t < 2; t++) {
                    float* d = acc[jp * 2 + t];
                    hmma(d, ah, wh[2 * t], wh[2 * t + 1]);
                    hmma(d, ah, wl[2 * t], wl[2 * t + 1]);
                    if (a_lo) hmma(d, al, wh[2 * t], wh[2 * t + 1]);
                }
            }
        }
    }
}

// write acc + bias into fp32 dst (qs/ks/vs)
__device__ __forceinline__ void epi_store(float (*dst)[132], float acc[4][4],
                                          const float* bias, int tid) {
    int lane = tid & 31, wid = tid >> 5;
    int r0 = (wid & 3) * 16 + (lane >> 2), nh = (wid >> 2) * 32, c0 = (lane & 3) * 2;
#pragma unroll
    for (int j = 0; j < 4; j++) {
        int c = nh + 8 * j + c0;
        float b0 = __ldg(bias + c), b1 = __ldg(bias + c + 1);
        dst[r0][c]         = acc[j][0] + b0;
        dst[r0][c + 1]     = acc[j][1] + b1;
        dst[r0 + 8][c]     = acc[j][2] + b0;
        dst[r0 + 8][c + 1] = acc[j][3] + b1;
    }
}
// xs += acc + bias
__device__ __forceinline__ void epi_resid(SMem* sm, float acc[4][4],
                                          const float* bias, int tid) {
    int lane = tid & 31, wid = tid >> 5;
    int r0 = (wid & 3) * 16 + (lane >> 2), nh = (wid >> 2) * 32, c0 = (lane & 3) * 2;
#pragma unroll
    for (int j = 0; j < 4; j++) {
        int c = nh + 8 * j + c0;
        float b0 = __ldg(bias + c), b1 = __ldg(bias + c + 1);
        sm->xs[r0][c]         += acc[j][0] + b0;
        sm->xs[r0][c + 1]     += acc[j][1] + b1;
        sm->xs[r0 + 8][c]     += acc[j][2] + b0;
        sm->xs[r0 + 8][c + 1] += acc[j][3] + b1;
    }
}
// cb = bf16(gelu(acc + b1))
__device__ __forceinline__ void epi_gelu(SMem* sm, float acc[4][4],
                                         const float* bias, int tid) {
    int lane = tid & 31, wid = tid >> 5;
    int r0 = (wid & 3) * 16 + (lane >> 2), nh = (wid >> 2) * 32, c0 = (lane & 3) * 2;
#pragma unroll
    for (int j = 0; j < 4; j++) {
        int c = nh + 8 * j + c0;
        float b0 = __ldg(bias + c), b1 = __ldg(bias + c + 1);
        __nv_bfloat162 p0, p1;
        p0.x = __float2bfloat16(gelu_exact(acc[j][0] + b0));
        p0.y = __float2bfloat16(gelu_exact(acc[j][1] + b1));
        p1.x = __float2bfloat16(gelu_exact(acc[j][2] + b0));
        p1.y = __float2bfloat16(gelu_exact(acc[j][3] + b1));
        *(__nv_bfloat162*)&sm->cb[r0][c]     = p0;
        *(__nv_bfloat162*)&sm->cb[r0 + 8][c] = p1;
    }
}

__device__ __forceinline__ void st_hilo(SMem* sm, int r, int c, float a, float b) {
    __nv_bfloat16 h0 = __float2bfloat16(a), h1 = __float2bfloat16(b);
    __nv_bfloat162 ph, pl;
    ph.x = h0; ph.y = h1;
    pl.x = __float2bfloat16(a - __bfloat162float(h0));
    pl.y = __float2bfloat16(b - __bfloat162float(h1));
    *(__nv_bfloat162*)&sm->ax[0][r][c] = ph;
    *(__nv_bfloat162*)&sm->ax[1][r][c] = pl;
}

// LayerNorm rows of xs (8 lanes/row), write xs AND ax hi/lo
__device__ void lnorm_conv(SMem* sm, const float* g, const float* b, int tid) {
    int row = tid >> 3, c0 = (tid & 7) << 4;
    float v[16];
    float s = 0.f;
#pragma unroll
    for (int i = 0; i < 4; i++) {
        float4 f = *(float4*)&sm->xs[row][c0 + i * 4];
        v[i*4] = f.x; v[i*4+1] = f.y; v[i*4+2] = f.z; v[i*4+3] = f.w;
        s += f.x + f.y + f.z + f.w;
    }
    s += __shfl_xor_sync(0xffffffffu, s, 1);
    s += __shfl_xor_sync(0xffffffffu, s, 2);
    s += __shfl_xor_sync(0xffffffffu, s, 4);
    float mu = s * (1.f / 128.f);
    float q = 0.f;
#pragma unroll
    for (int j = 0; j < 16; j++) { v[j] -= mu; q += v[j] * v[j]; }
    q += __shfl_xor_sync(0xffffffffu, q, 1);
    q += __shfl_xor_sync(0xffffffffu, q, 2);
    q += __shfl_xor_sync(0xffffffffu, q, 4);
    float inv = rsqrtf(q * (1.f / 128.f) + LNEPS);
#pragma unroll
    for (int j = 0; j < 16; j += 2) {
        int c = c0 + j;
        float y0 = v[j]   * inv * __ldg(g + c)     + __ldg(b + c);
        float y1 = v[j+1] * inv * __ldg(g + c + 1) + __ldg(b + c + 1);
        sm->xs[row][c] = y0; sm->xs[row][c + 1] = y1;
        st_hilo(sm, row, c, y0, y1);
    }
}

__device__ void conv_ax(SMem* sm, int tid) {
    int row = tid >> 3, c0 = (tid & 7) << 4;
#pragma unroll
    for (int j = 0; j < 16; j += 2)
        st_hilo(sm, row, c0 + j, sm->xs[row][c0 + j], sm->xs[row][c0 + j + 1]);
}

#define ZACC(A) do { _Pragma("unroll") for (int _i = 0; _i < 4; _i++) \
    { (A)[_i][0]=0.f;(A)[_i][1]=0.f;(A)[_i][2]=0.f;(A)[_i][3]=0.f; } } while (0)

__global__ void __launch_bounds__(NTHR, 1)
mixer_kernel(const float* __restrict__ z0, const float* __restrict__ z1,
             const float* __restrict__ z2, const float* __restrict__ cls,
             const float* __restrict__ bqkv, const float* __restrict__ bo,
             const float* __restrict__ b1,  const float* __restrict__ b2,
             const float* __restrict__ ln1g, const float* __restrict__ ln1b,
             const float* __restrict__ ln2g, const float* __restrict__ ln2b,
             float* __restrict__ out)
{
    extern __shared__ char smraw[];
    SMem* sm = (SMem*)smraw;
    const int tid = threadIdx.x;
    const int seq0 = blockIdx.x * GSEQ;

    stage_chunk(sm, 0, 0, 0, tid);   // layer-0 Wq chunk0 (k32)

    // tokens -> xs: row 4g+s; s=0 CLS else z_{s-1}[seq0+g]
#pragma unroll
    for (int u = 0; u < 4; u++) {
        int idx = u * NTHR + tid, row = idx >> 5, c4 = (idx & 31) << 2;
        int g = row >> 2, s = row & 3;
        float4 v;
        if (s == 0) v = *(const float4*)(cls + c4);
        else {
            const float* zp = (s == 1) ? z0 : (s == 2) ? z1 : z2;
            v = *(const float4*)(zp + (long)(seq0 + g) * 128 + c4);
        }
        *(float4*)&sm->xs[row][c4] = v;
    }
    __syncthreads();
    conv_ax(sm, tid);

    float acc[4][4], facc[4][4];

    for (int l = 0; l < 2; l++) {
        int sb = 12 * l;
        // ---- QKV ----
        ZACC(acc); gemm(sm, sm->ax[0], sm->ax[1], sb + 0, sb + 1, acc, tid);
        epi_store(sm->qs, acc, bqkv + l * 384, tid);
        ZACC(acc); gemm(sm, sm->ax[0], sm->ax[1], sb + 1, sb + 2, acc, tid);
        epi_store(sm->ks, acc, bqkv + l * 384 + 128, tid);
        ZACC(acc); gemm(sm, sm->ax[0], sm->ax[1], sb + 2, sb + 3, acc, tid);
        epi_store(sm->vs, acc, bqkv + l * 384 + 256, tid);
        __syncthreads();

        // ---- attention: one thread per (seq, head); writes ax hi/lo ----
        if (tid < 128) {
            int g = tid >> 3, h = tid & 7;
            int r0 = g * 4, co = h * 16;
            float sc[4][4];
#pragma unroll
            for (int i = 0; i < 4; i++)
#pragma unroll
                for (int j = 0; j < 4; j++) {
                    float s = 0.f;
#pragma unroll
                    for (int e = 0; e < 16; e++)
                        s += sm->qs[r0 + i][co + e] * sm->ks[r0 + j][co + e];
                    sc[i][j] = s * 0.25f;
                }
#pragma unroll
            for (int i = 0; i < 4; i++) {
                float m = fmaxf(fmaxf(sc[i][0], sc[i][1]), fmaxf(sc[i][2], sc[i][3]));
                float den = 0.f;
#pragma unroll
                for (int j = 0; j < 4; j++) { sc[i][j] = expf(sc[i][j] - m); den += sc[i][j]; }
                float inv = 1.f / den;
#pragma unroll
                for (int j = 0; j < 4; j++) sc[i][j] *= inv;
            }
#pragma unroll
            for (int i = 0; i < 4; i++)
#pragma unroll
                for (int e = 0; e < 16; e += 2) {
                    float o0 = 0.f, o1 = 0.f;
#pragma unroll
                    for (int j = 0; j < 4; j++) {
                        o0 += sc[i][j] * sm->vs[r0 + j][co + e];
                        o1 += sc[i][j] * sm->vs[r0 + j][co + e + 1];
                    }
                    st_hilo(sm, r0 + i, co + e, o0, o1);
                }
        }
        // ax published by Wo gemm's chunk-0 barrier

        // ---- Wo + residual + LN1 ----
        ZACC(acc); gemm(sm, sm->ax[0], sm->ax[1], sb + 3, sb + 4, acc, tid);
        epi_resid(sm, acc, bo + l * 128, tid);
        __syncthreads();
        lnorm_conv(sm, ln1g + l * 128, ln1b + l * 128, tid);

        // ---- FFN ----
        ZACC(facc);
        for (int fc = 0; fc < 4; fc++) {
            ZACC(acc);
            gemm(sm, sm->ax[0], sm->ax[1], sb + 4 + 2 * fc, sb + 5 + 2 * fc, acc, tid);
            epi_gelu(sm, acc, b1 + l * 512 + fc * 128, tid);
            int nxt = (fc < 3) ? sb + 6 + 2 * fc : (l == 0 ? 12 : -1);
            gemm(sm, sm->cb, nullptr, sb + 5 + 2 * fc, nxt, facc, tid);
        }
        epi_resid(sm, facc, b2 + l * 128, tid);
        __syncthreads();
        lnorm_conv(sm, ln2g + l * 128, ln2b + l * 128, tid);
        __syncthreads();
    }

    // CLS rows 4g -> out: 512 threads, one float4 each
    {
        int g = tid >> 5, c4 = (tid & 31) << 2;
        *(float4*)(out + (long)(seq0 + g) * 128 + c4) = *(float4*)&sm->xs[4 * g][c4];
    }
}

extern "C" void kernel_launch(void* const* d_in, const int* in_sizes, int n_in,
                              void* d_out, int out_size)
{
    (void)in_sizes; (void)n_in; (void)out_size;
    const float* z0   = (const float*)d_in[0];
    const float* z1   = (const float*)d_in[1];
    const float* z2   = (const float*)d_in[2];
    const float* cls  = (const float*)d_in[3];
    const float* Wqkv = (const float*)d_in[4];
    const float* bqkv = (const float*)d_in[5];
    const float* Wo   = (const float*)d_in[6];
    const float* bo   = (const float*)d_in[7];
    const float* W1   = (const float*)d_in[8];
    const float* b1   = (const float*)d_in[9];
    const float* W2   = (const float*)d_in[10];
    const float* b2   = (const float*)d_in[11];
    const float* ln1g = (const float*)d_in[12];
    const float* ln1b = (const float*)d_in[13];
    const float* ln2g = (const float*)d_in[14];
    const float* ln2b = (const float*)d_in[15];
    float* out = (float*)d_out;

    wsplit_kernel<<<(NTILE * 16384 + 383) / 384, 384>>>(Wqkv, Wo, W1, W2);

    cudaFuncSetAttribute(mixer_kernel,
                         cudaFuncAttributeMaxDynamicSharedMemorySize, (int)sizeof(SMem));
    mixer_kernel<<<NSEQ / GSEQ, NTHR, sizeof(SMem)>>>(
        z0, z1, z2, cls, bqkv, bo, b1, b2, ln1g, ln1b, ln2g, ln2b, out);
}

// round 15
// speedup vs baseline: 2.1926x; 1.0973x over previous
#include <cuda_runtime.h>
#include <cuda_fp16.h>

// EpochMixer R14: HMMA fp16 2-pass split (A single fp16, W = hi+lo fp16),
// 512 threads / 16 warps (m16xn32/warp), k32 chunks per barrier, 2-slot ring.

#define NSEQ  32768
#define GSEQ  16
#define NTHR  512
#define NTILE 24
#define LNEPS 1e-5f

// pre-split weights, [slot][hi/lo][n][k] row-major fp16.
// slots per layer: Wq,Wk,Wv,Wo, W1f0,W2f0,W1f1,W2f1,W1f2,W2f2,W1f3,W2f3
__device__ __half g_wt[NTILE][2][128][128];

struct SMem {
    float xs[64][132];            // residual stream (fp32)
    float qs[64][132];
    float ks[64][132];
    float vs[64][132];
    __half ax[64][136];           // A operand (single fp16)
    __half cb[64][136];           // gelu-h operand (fp16)
    __half ring[2][2][128][40];   // k32 weight chunks, hi/lo, 2-slot ring (80B rows)
};

__global__ void wsplit_kernel(const float* __restrict__ Wqkv, const float* __restrict__ Wo,
                              const float* __restrict__ W1,   const float* __restrict__ W2) {
    int idx = blockIdx.x * blockDim.x + threadIdx.x;
    if (idx >= NTILE * 16384) return;
    int t = idx >> 14, e = idx & 16383, n = e >> 7, k = e & 127;
    int l = t / 12, tt = t % 12;
    float w;
    if (tt < 3)       w = Wqkv[((l * 3 + tt) * 128 + n) * 128 + k];
    else if (tt == 3) w = Wo[(l * 128 + n) * 128 + k];
    else { int q = tt - 4, fc = q >> 1;
        if (!(q & 1)) w = W1[(l * 512 + fc * 128 + n) * 128 + k];
        else          w = W2[(l * 128 + n) * 512 + fc * 128 + k]; }
    __half hi = __float2half(w);
    g_wt[t][0][n][k] = hi;
    g_wt[t][1][n][k] = __float2half(w - __half2float(hi));
}

__device__ __forceinline__ unsigned smaddr(const void* p) {
    return (unsigned)__cvta_generic_to_shared(p);
}
__device__ __forceinline__ void ldsm4(unsigned a, unsigned r[4]) {
    asm volatile("ldmatrix.sync.aligned.m8n8.x4.shared.b16 {%0,%1,%2,%3}, [%4];"
                 : "=r"(r[0]), "=r"(r[1]), "=r"(r[2]), "=r"(r[3]) : "r"(a));
}
__device__ __forceinline__ void hmma(float d[4], const unsigned a[4],
                                     unsigned b0, unsigned b1) {
    asm volatile("mma.sync.aligned.m16n8k16.row.col.f32.f16.f16.f32 "
                 "{%0,%1,%2,%3},{%4,%5,%6,%7},{%8,%9},{%0,%1,%2,%3};"
                 : "+f"(d[0]), "+f"(d[1]), "+f"(d[2]), "+f"(d[3])
                 : "r"(a[0]), "r"(a[1]), "r"(a[2]), "r"(a[3]), "r"(b0), "r"(b1));
}
__device__ __forceinline__ float gelu_exact(float v) {
    return 0.5f * v * (1.0f + erff(v * 0.70710678118654752f));
}

// stage one k32 chunk (hi+lo, 128 rows x 64B = 1024 x 16B) into ring slot s2
__device__ __forceinline__ void stage_chunk(SMem* sm, int s2, int slot, int kc32, int tid) {
#pragma unroll
    for (int u = 0; u < 2; u++) {
        int idx = u * NTHR + tid;          // 0..1023
        int h = idx >> 9, rem = idx & 511, n = rem >> 2, x = rem & 3;
        unsigned dst = smaddr(&sm->ring[s2][h][n][x * 8]);
        const void* src = &g_wt[slot][h][n][kc32 * 32 + x * 8];
        asm volatile("cp.async.cg.shared.global [%0], [%1], 16;"
                     :: "r"(dst), "l"(src) : "memory");
    }
    asm volatile("cp.async.commit_group;" ::: "memory");
}

// acc[4][4] += A[64][128] @ W(slot)^T (this warp's m16 x n32 slice), 2-pass:
// A fp16 single, W hi + lo. Entry invariant: chunk0 (k32) of slot staged into
// ring slot 0, sole outstanding group. Exit (next_slot>=0): its chunk0 in slot 0.
__device__ void gemm(SMem* sm, const __half (*a_t)[136],
                     int slot, int next_slot, float acc[4][4], int tid)
{
    const int lane = tid & 31, wid = tid >> 5;
    const int mw = (wid & 3) * 16, nh = (wid >> 2) * 32;
    const int arow = mw + (lane & 15), acol = (lane >> 4) * 8;
    const int brow = (lane & 7) + 8 * (lane >> 4), bkoff = ((lane >> 3) & 1) * 8;

#pragma unroll 1
    for (int c = 0; c < 4; c++) {
        asm volatile("cp.async.wait_group 0;" ::: "memory");
        __syncthreads();
        if (c < 3)               stage_chunk(sm, (c + 1) & 1, slot, c + 1, tid);
        else if (next_slot >= 0) stage_chunk(sm, 0, next_slot, 0, tid);

        const int cs = c & 1;
#pragma unroll
        for (int s = 0; s < 2; s++) {
            const int kc = c * 32 + s * 16, ko = s * 16 + bkoff;
            unsigned ah[4];
            ldsm4(smaddr(&a_t[arow][kc + acol]), ah);
#pragma unroll
            for (int jp = 0; jp < 2; jp++) {
                int nr = nh + jp * 16 + brow;
                unsigned wh[4], wl[4];
                ldsm4(smaddr(&sm->ring[cs][0][nr][ko]), wh);
                ldsm4(smaddr(&sm->ring[cs][1][nr][ko]), wl);
#pragma unroll
                for (int t = 0; t < 2; t++) {
                    float* d = acc[jp * 2 + t];
                    hmma(d, ah, wh[2 * t], wh[2 * t + 1]);
                    hmma(d, ah, wl[2 * t], wl[2 * t + 1]);
                }
            }
        }
    }
}

// write acc + bias into fp32 dst (qs/ks/vs)
__device__ __forceinline__ void epi_store(float (*dst)[132], float acc[4][4],
                                          const float* bias, int tid) {
    int lane = tid & 31, wid = tid >> 5;
    int r0 = (wid & 3) * 16 + (lane >> 2), nh = (wid >> 2) * 32, c0 = (lane & 3) * 2;
#pragma unroll
    for (int j = 0; j < 4; j++) {
        int c = nh + 8 * j + c0;
        float b0 = __ldg(bias + c), b1 = __ldg(bias + c + 1);
        dst[r0][c]         = acc[j][0] + b0;
        dst[r0][c + 1]     = acc[j][1] + b1;
        dst[r0 + 8][c]     = acc[j][2] + b0;
        dst[r0 + 8][c + 1] = acc[j][3] + b1;
    }
}
// xs += acc + bias
__device__ __forceinline__ void epi_resid(SMem* sm, float acc[4][4],
                                          const float* bias, int tid) {
    int lane = tid & 31, wid = tid >> 5;
    int r0 = (wid & 3) * 16 + (lane >> 2), nh = (wid >> 2) * 32, c0 = (lane & 3) * 2;
#pragma unroll
    for (int j = 0; j < 4; j++) {
        int c = nh + 8 * j + c0;
        float b0 = __ldg(bias + c), b1 = __ldg(bias + c + 1);
        sm->xs[r0][c]         += acc[j][0] + b0;
        sm->xs[r0][c + 1]     += acc[j][1] + b1;
        sm->xs[r0 + 8][c]     += acc[j][2] + b0;
        sm->xs[r0 + 8][c + 1] += acc[j][3] + b1;
    }
}
// cb = fp16(gelu(acc + b1))
__device__ __forceinline__ void epi_gelu(SMem* sm, float acc[4][4],
                                         const float* bias, int tid) {
    int lane = tid & 31, wid = tid >> 5;
    int r0 = (wid & 3) * 16 + (lane >> 2), nh = (wid >> 2) * 32, c0 = (lane & 3) * 2;
#pragma unroll
    for (int j = 0; j < 4; j++) {
        int c = nh + 8 * j + c0;
        float b0 = __ldg(bias + c), b1 = __ldg(bias + c + 1);
        *(__half2*)&sm->cb[r0][c] =
            __floats2half2_rn(gelu_exact(acc[j][0] + b0), gelu_exact(acc[j][1] + b1));
        *(__half2*)&sm->cb[r0 + 8][c] =
            __floats2half2_rn(gelu_exact(acc[j][2] + b0), gelu_exact(acc[j][3] + b1));
    }
}

__device__ __forceinline__ void st_ax(SMem* sm, int r, int c, float a, float b) {
    *(__half2*)&sm->ax[r][c] = __floats2half2_rn(a, b);
}

// LayerNorm rows of xs (8 lanes/row), write xs AND ax fp16
__device__ void lnorm_conv(SMem* sm, const float* g, const float* b, int tid) {
    int row = tid >> 3, c0 = (tid & 7) << 4;
    float v[16];
    float s = 0.f;
#pragma unroll
    for (int i = 0; i < 4; i++) {
        float4 f = *(float4*)&sm->xs[row][c0 + i * 4];
        v[i*4] = f.x; v[i*4+1] = f.y; v[i*4+2] = f.z; v[i*4+3] = f.w;
        s += f.x + f.y + f.z + f.w;
    }
    s += __shfl_xor_sync(0xffffffffu, s, 1);
    s += __shfl_xor_sync(0xffffffffu, s, 2);
    s += __shfl_xor_sync(0xffffffffu, s, 4);
    float mu = s * (1.f / 128.f);
    float q = 0.f;
#pragma unroll
    for (int j = 0; j < 16; j++) { v[j] -= mu; q += v[j] * v[j]; }
    q += __shfl_xor_sync(0xffffffffu, q, 1);
    q += __shfl_xor_sync(0xffffffffu, q, 2);
    q += __shfl_xor_sync(0xffffffffu, q, 4);
    float inv = rsqrtf(q * (1.f / 128.f) + LNEPS);
#pragma unroll
    for (int j = 0; j < 16; j += 2) {
        int c = c0 + j;
        float y0 = v[j]   * inv * __ldg(g + c)     + __ldg(b + c);
        float y1 = v[j+1] * inv * __ldg(g + c + 1) + __ldg(b + c + 1);
        sm->xs[row][c] = y0; sm->xs[row][c + 1] = y1;
        st_ax(sm, row, c, y0, y1);
    }
}

__device__ void conv_ax(SMem* sm, int tid) {
    int row = tid >> 3, c0 = (tid & 7) << 4;
#pragma unroll
    for (int j = 0; j < 16; j += 2)
        st_ax(sm, row, c0 + j, sm->xs[row][c0 + j], sm->xs[row][c0 + j + 1]);
}

#define ZACC(A) do { _Pragma("unroll") for (int _i = 0; _i < 4; _i++) \
    { (A)[_i][0]=0.f;(A)[_i][1]=0.f;(A)[_i][2]=0.f;(A)[_i][3]=0.f; } } while (0)

__global__ void __launch_bounds__(NTHR, 1)
mixer_kernel(const float* __restrict__ z0, const float* __restrict__ z1,
             const float* __restrict__ z2, const float* __restrict__ cls,
             const float* __restrict__ bqkv, const float* __restrict__ bo,
             const float* __restrict__ b1,  const float* __restrict__ b2,
             const float* __restrict__ ln1g, const float* __restrict__ ln1b,
             const float* __restrict__ ln2g, const float* __restrict__ ln2b,
             float* __restrict__ out)
{
    extern __shared__ char smraw[];
    SMem* sm = (SMem*)smraw;
    const int tid = threadIdx.x;
    const int seq0 = blockIdx.x * GSEQ;

    stage_chunk(sm, 0, 0, 0, tid);   // layer-0 Wq chunk0 (k32)

    // tokens -> xs: row 4g+s; s=0 CLS else z_{s-1}[seq0+g]
#pragma unroll
    for (int u = 0; u < 4; u++) {
        int idx = u * NTHR + tid, row = idx >> 5, c4 = (idx & 31) << 2;
        int g = row >> 2, s = row & 3;
        float4 v;
        if (s == 0) v = *(const float4*)(cls + c4);
        else {
            const float* zp = (s == 1) ? z0 : (s == 2) ? z1 : z2;
            v = *(const float4*)(zp + (long)(seq0 + g) * 128 + c4);
        }
        *(float4*)&sm->xs[row][c4] = v;
    }
    __syncthreads();
    conv_ax(sm, tid);

    float acc[4][4], facc[4][4];

    for (int l = 0; l < 2; l++) {
        int sb = 12 * l;
        // ---- QKV ----
        ZACC(acc); gemm(sm, sm->ax, sb + 0, sb + 1, acc, tid);
        epi_store(sm->qs, acc, bqkv + l * 384, tid);
        ZACC(acc); gemm(sm, sm->ax, sb + 1, sb + 2, acc, tid);
        epi_store(sm->ks, acc, bqkv + l * 384 + 128, tid);
        ZACC(acc); gemm(sm, sm->ax, sb + 2, sb + 3, acc, tid);
        epi_store(sm->vs, acc, bqkv + l * 384 + 256, tid);
        __syncthreads();

        // ---- attention: one thread per (seq, head); writes ax fp16 ----
        if (tid < 128) {
            int g = tid >> 3, h = tid & 7;
            int r0 = g * 4, co = h * 16;
            float sc[4][4];
#pragma unroll
            for (int i = 0; i < 4; i++)
#pragma unroll
                for (int j = 0; j < 4; j++) {
                    float s = 0.f;
#pragma unroll
                    for (int e = 0; e < 16; e++)
                        s += sm->qs[r0 + i][co + e] * sm->ks[r0 + j][co + e];
                    sc[i][j] = s * 0.25f;
                }
#pragma unroll
            for (int i = 0; i < 4; i++) {
                float m = fmaxf(fmaxf(sc[i][0], sc[i][1]), fmaxf(sc[i][2], sc[i][3]));
                float den = 0.f;
#pragma unroll
                for (int j = 0; j < 4; j++) { sc[i][j] = expf(sc[i][j] - m); den += sc[i][j]; }
                float inv = 1.f / den;
#pragma unroll
                for (int j = 0; j < 4; j++) sc[i][j] *= inv;
            }
#pragma unroll
            for (int i = 0; i < 4; i++)
#pragma unroll
                for (int e = 0; e < 16; e += 2) {
                    float o0 = 0.f, o1 = 0.f;
#pragma unroll
                    for (int j = 0; j < 4; j++) {
                        o0 += sc[i][j] * sm->vs[r0 + j][co + e];
                        o1 += sc[i][j] * sm->vs[r0 + j][co + e + 1];
                    }
                    st_ax(sm, r0 + i, co + e, o0, o1);
                }
        }
        // ax published by Wo gemm's chunk-0 barrier

        // ---- Wo + residual + LN1 ----
        ZACC(acc); gemm(sm, sm->ax, sb + 3, sb + 4, acc, tid);
        epi_resid(sm, acc, bo + l * 128, tid);
        __syncthreads();
        lnorm_conv(sm, ln1g + l * 128, ln1b + l * 128, tid);

        // ---- FFN ----
        ZACC(facc);
        for (int fc = 0; fc < 4; fc++) {
            ZACC(acc);
            gemm(sm, sm->ax, sb + 4 + 2 * fc, sb + 5 + 2 * fc, acc, tid);
            epi_gelu(sm, acc, b1 + l * 512 + fc * 128, tid);
            int nxt = (fc < 3) ? sb + 6 + 2 * fc : (l == 0 ? 12 : -1);
            gemm(sm, sm->cb, sb + 5 + 2 * fc, nxt, facc, tid);
        }
        epi_resid(sm, facc, b2 + l * 128, tid);
        __syncthreads();
        lnorm_conv(sm, ln2g + l * 128, ln2b + l * 128, tid);
        __syncthreads();
    }

    // CLS rows 4g -> out: 512 threads, one float4 each
    {
        int g = tid >> 5, c4 = (tid & 31) << 2;
        *(float4*)(out + (long)(seq0 + g) * 128 + c4) = *(float4*)&sm->xs[4 * g][c4];
    }
}

extern "C" void kernel_launch(void* const* d_in, const int* in_sizes, int n_in,
                              void* d_out, int out_size)
{
    (void)in_sizes; (void)n_in; (void)out_size;
    const float* z0   = (const float*)d_in[0];
    const float* z1   = (const float*)d_in[1];
    const float* z2   = (const float*)d_in[2];
    const float* cls  = (const float*)d_in[3];
    const float* Wqkv = (const float*)d_in[4];
    const float* bqkv = (const float*)d_in[5];
    const float* Wo   = (const float*)d_in[6];
    const float* bo   = (const float*)d_in[7];
    const float* W1   = (const float*)d_in[8];
    const float* b1   = (const float*)d_in[9];
    const float* W2   = (const float*)d_in[10];
    const float* b2   = (const float*)d_in[11];
    const float* ln1g = (const float*)d_in[12];
    const float* ln1b = (const float*)d_in[13];
    const float* ln2g = (const float*)d_in[14];
    const float* ln2b = (const float*)d_in[15];
    float* out = (float*)d_out;

    wsplit_kernel<<<(NTILE * 16384 + 383) / 384, 384>>>(Wqkv, Wo, W1, W2);

    cudaFuncSetAttribute(mixer_kernel,
                         cudaFuncAttributeMaxDynamicSharedMemorySize, (int)sizeof(SMem));
    mixer_kernel<<<NSEQ / GSEQ, NTHR, sizeof(SMem)>>>(
        z0, z1, z2, cls, bqkv, bo, b1, b2, ln1g, ln1b, ln2g, ln2b, out);
}

// round 17
// speedup vs baseline: 2.4683x; 1.1257x over previous
#include <cuda_runtime.h>
#include <cuda_fp16.h>

// EpochMixer R15: HMMA fp16, per-slot precision: QKV W = hi+lo 2-pass,
// Wo/FFN W = single fp16 1-pass. 512 threads / 16 warps (m16xn32/warp),
// k32 chunks per barrier, 2-slot ring, stage-after-sync.

#define NSEQ  32768
#define GSEQ  16
#define NTHR  512
#define NTILE 24
#define LNEPS 1e-5f

// pre-split weights, [slot][hi/lo][n][k] row-major fp16.
// slots per layer: Wq,Wk,Wv,Wo, W1f0,W2f0,W1f1,W2f1,W1f2,W2f2,W1f3,W2f3
__device__ __half g_wt[NTILE][2][128][128];

// 2-pass (hi+lo) only for Wq,Wk,Wv of each layer
__device__ __forceinline__ bool slot_two(int slot) { return (slot % 12) < 3; }

struct SMem {
    float xs[64][132];            // residual stream (fp32)
    float qs[64][132];
    float ks[64][132];
    float vs[64][132];
    __half ax[64][136];           // A operand (single fp16)
    __half cb[64][136];           // gelu-h operand (fp16)
    __half ring[2][2][128][40];   // k32 weight chunks, hi/lo, 2-slot ring (80B rows)
};

__global__ void wsplit_kernel(const float* __restrict__ Wqkv, const float* __restrict__ Wo,
                              const float* __restrict__ W1,   const float* __restrict__ W2) {
    int idx = blockIdx.x * blockDim.x + threadIdx.x;
    if (idx >= NTILE * 16384) return;
    int t = idx >> 14, e = idx & 16383, n = e >> 7, k = e & 127;
    int l = t / 12, tt = t % 12;
    float w;
    if (tt < 3)       w = Wqkv[((l * 3 + tt) * 128 + n) * 128 + k];
    else if (tt == 3) w = Wo[(l * 128 + n) * 128 + k];
    else { int q = tt - 4, fc = q >> 1;
        if (!(q & 1)) w = W1[(l * 512 + fc * 128 + n) * 128 + k];
        else          w = W2[(l * 128 + n) * 512 + fc * 128 + k]; }
    __half hi = __float2half(w);
    g_wt[t][0][n][k] = hi;
    g_wt[t][1][n][k] = __float2half(w - __half2float(hi));
}

__device__ __forceinline__ unsigned smaddr(const void* p) {
    return (unsigned)__cvta_generic_to_shared(p);
}
__device__ __forceinline__ void ldsm4(unsigned a, unsigned r[4]) {
    asm volatile("ldmatrix.sync.aligned.m8n8.x4.shared.b16 {%0,%1,%2,%3}, [%4];"
                 : "=r"(r[0]), "=r"(r[1]), "=r"(r[2]), "=r"(r[3]) : "r"(a));
}
__device__ __forceinline__ void hmma(float d[4], const unsigned a[4],
                                     unsigned b0, unsigned b1) {
    asm volatile("mma.sync.aligned.m16n8k16.row.col.f32.f16.f16.f32 "
                 "{%0,%1,%2,%3},{%4,%5,%6,%7},{%8,%9},{%0,%1,%2,%3};"
                 : "+f"(d[0]), "+f"(d[1]), "+f"(d[2]), "+f"(d[3])
                 : "r"(a[0]), "r"(a[1]), "r"(a[2]), "r"(a[3]), "r"(b0), "r"(b1));
}
__device__ __forceinline__ float gelu_exact(float v) {
    return 0.5f * v * (1.0f + erff(v * 0.70710678118654752f));
}

// stage one k32 chunk into ring slot s2; hi only, or hi+lo when two.
__device__ __forceinline__ void stage_chunk(SMem* sm, int s2, int slot, int kc32,
                                            int tid, bool two) {
    {   // hi half: 512 x 16B, one per thread
        int n = tid >> 2, x = tid & 3;
        unsigned dst = smaddr(&sm->ring[s2][0][n][x * 8]);
        const void* src = &g_wt[slot][0][n][kc32 * 32 + x * 8];
        asm volatile("cp.async.cg.shared.global [%0], [%1], 16;"
                     :: "r"(dst), "l"(src) : "memory");
    }
    if (two) {
        int n = tid >> 2, x = tid & 3;
        unsigned dst = smaddr(&sm->ring[s2][1][n][x * 8]);
        const void* src = &g_wt[slot][1][n][kc32 * 32 + x * 8];
        asm volatile("cp.async.cg.shared.global [%0], [%1], 16;"
                     :: "r"(dst), "l"(src) : "memory");
    }
    asm volatile("cp.async.commit_group;" ::: "memory");
}

// acc[4][4] += A[64][128] @ W(slot)^T (this warp's m16 x n32 slice).
// W passes = 2 iff slot_two(slot). Entry invariant: chunk0 of slot staged into
// ring slot 0, sole outstanding group. Exit (next_slot>=0): its chunk0 in slot 0.
__device__ void gemm(SMem* sm, const __half (*a_t)[136],
                     int slot, int next_slot, float acc[4][4], int tid)
{
    const int lane = tid & 31, wid = tid >> 5;
    const int mw = (wid & 3) * 16, nh = (wid >> 2) * 32;
    const int arow = mw + (lane & 15), acol = (lane >> 4) * 8;
    const int brow = (lane & 7) + 8 * (lane >> 4), bkoff = ((lane >> 3) & 1) * 8;
    const bool two = slot_two(slot);

#pragma unroll 1
    for (int c = 0; c < 4; c++) {
        asm volatile("cp.async.wait_group 0;" ::: "memory");
        __syncthreads();
        if (c < 3)               stage_chunk(sm, (c + 1) & 1, slot, c + 1, tid, two);
        else if (next_slot >= 0) stage_chunk(sm, 0, next_slot, 0, tid, slot_two(next_slot));

        const int cs = c & 1;
#pragma unroll
        for (int s = 0; s < 2; s++) {
            const int kc = c * 32 + s * 16, ko = s * 16 + bkoff;
            unsigned ah[4];
            ldsm4(smaddr(&a_t[arow][kc + acol]), ah);
#pragma unroll
            for (int jp = 0; jp < 2; jp++) {
                int nr = nh + jp * 16 + brow;
                unsigned wh[4];
                ldsm4(smaddr(&sm->ring[cs][0][nr][ko]), wh);
                float* d0 = acc[jp * 2];
                float* d1 = acc[jp * 2 + 1];
                hmma(d0, ah, wh[0], wh[1]);
                hmma(d1, ah, wh[2], wh[3]);
                if (two) {
                    unsigned wl[4];
                    ldsm4(smaddr(&sm->ring[cs][1][nr][ko]), wl);
                    hmma(d0, ah, wl[0], wl[1]);
                    hmma(d1, ah, wl[2], wl[3]);
                }
            }
        }
    }
}

// write acc + bias into fp32 dst (qs/ks/vs)
__device__ __forceinline__ void epi_store(float (*dst)[132], float acc[4][4],
                                          const float* bias, int tid) {
    int lane = tid & 31, wid = tid >> 5;
    int r0 = (wid & 3) * 16 + (lane >> 2), nh = (wid >> 2) * 32, c0 = (lane & 3) * 2;
#pragma unroll
    for (int j = 0; j < 4; j++) {
        int c = nh + 8 * j + c0;
        float b0 = __ldg(bias + c), b1 = __ldg(bias + c + 1);
        dst[r0][c]         = acc[j][0] + b0;
        dst[r0][c + 1]     = acc[j][1] + b1;
        dst[r0 + 8][c]     = acc[j][2] + b0;
        dst[r0 + 8][c + 1] = acc[j][3] + b1;
    }
}
// xs += acc + bias
__device__ __forceinline__ void epi_resid(SMem* sm, float acc[4][4],
                                          const float* bias, int tid) {
    int lane = tid & 31, wid = tid >> 5;
    int r0 = (wid & 3) * 16 + (lane >> 2), nh = (wid >> 2) * 32, c0 = (lane & 3) * 2;
#pragma unroll
    for (int j = 0; j < 4; j++) {
        int c = nh + 8 * j + c0;
        float b0 = __ldg(bias + c), b1 = __ldg(bias + c + 1);
        sm->xs[r0][c]         += acc[j][0] + b0;
        sm->xs[r0][c + 1]     += acc[j][1] + b1;
        sm->xs[r0 + 8][c]     += acc[j][2] + b0;
        sm->xs[r0 + 8][c + 1] += acc[j][3] + b1;
    }
}
// cb = fp16(gelu(acc + b1))
__device__ __forceinline__ void epi_gelu(SMem* sm, float acc[4][4],
                                         const float* bias, int tid) {
    int lane = tid & 31, wid = tid >> 5;
    int r0 = (wid & 3) * 16 + (lane >> 2), nh = (wid >> 2) * 32, c0 = (lane & 3) * 2;
#pragma unroll
    for (int j = 0; j < 4; j++) {
        int c = nh + 8 * j + c0;
        float b0 = __ldg(bias + c), b1 = __ldg(bias + c + 1);
        *(__half2*)&sm->cb[r0][c] =
            __floats2half2_rn(gelu_exact(acc[j][0] + b0), gelu_exact(acc[j][1] + b1));
        *(__half2*)&sm->cb[r0 + 8][c] =
            __floats2half2_rn(gelu_exact(acc[j][2] + b0), gelu_exact(acc[j][3] + b1));
    }
}

__device__ __forceinline__ void st_ax(SMem* sm, int r, int c, float a, float b) {
    *(__half2*)&sm->ax[r][c] = __floats2half2_rn(a, b);
}

// LayerNorm rows of xs (8 lanes/row), write xs AND ax fp16
__device__ void lnorm_conv(SMem* sm, const float* g, const float* b, int tid) {
    int row = tid >> 3, c0 = (tid & 7) << 4;
    float v[16];
    float s = 0.f;
#pragma unroll
    for (int i = 0; i < 4; i++) {
        float4 f = *(float4*)&sm->xs[row][c0 + i * 4];
        v[i*4] = f.x; v[i*4+1] = f.y; v[i*4+2] = f.z; v[i*4+3] = f.w;
        s += f.x + f.y + f.z + f.w;
    }
    s += __shfl_xor_sync(0xffffffffu, s, 1);
    s += __shfl_xor_sync(0xffffffffu, s, 2);
    s += __shfl_xor_sync(0xffffffffu, s, 4);
    float mu = s * (1.f / 128.f);
    float q = 0.f;
#pragma unroll
    for (int j = 0; j < 16; j++) { v[j] -= mu; q += v[j] * v[j]; }
    q += __shfl_xor_sync(0xffffffffu, q, 1);
    q += __shfl_xor_sync(0xffffffffu, q, 2);
    q += __shfl_xor_sync(0xffffffffu, q, 4);
    float inv = rsqrtf(q * (1.f / 128.f) + LNEPS);
#pragma unroll
    for (int j = 0; j < 16; j += 2) {
        int c = c0 + j;
        float y0 = v[j]   * inv * __ldg(g + c)     + __ldg(b + c);
        float y1 = v[j+1] * inv * __ldg(g + c + 1) + __ldg(b + c + 1);
        sm->xs[row][c] = y0; sm->xs[row][c + 1] = y1;
        st_ax(sm, row, c, y0, y1);
    }
}

__device__ void conv_ax(SMem* sm, int tid) {
    int row = tid >> 3, c0 = (tid & 7) << 4;
#pragma unroll
    for (int j = 0; j < 16; j += 2)
        st_ax(sm, row, c0 + j, sm->xs[row][c0 + j], sm->xs[row][c0 + j + 1]);
}

#define ZACC(A) do { _Pragma("unroll") for (int _i = 0; _i < 4; _i++) \
    { (A)[_i][0]=0.f;(A)[_i][1]=0.f;(A)[_i][2]=0.f;(A)[_i][3]=0.f; } } while (0)

__global__ void __launch_bounds__(NTHR, 1)
mixer_kernel(const float* __restrict__ z0, const float* __restrict__ z1,
             const float* __restrict__ z2, const float* __restrict__ cls,
             const float* __restrict__ bqkv, const float* __restrict__ bo,
             const float* __restrict__ b1,  const float* __restrict__ b2,
             const float* __restrict__ ln1g, const float* __restrict__ ln1b,
             const float* __restrict__ ln2g, const float* __restrict__ ln2b,
             float* __restrict__ out)
{
    extern __shared__ char smraw[];
    SMem* sm = (SMem*)smraw;
    const int tid = threadIdx.x;
    const int seq0 = blockIdx.x * GSEQ;

    stage_chunk(sm, 0, 0, 0, tid, true);   // layer-0 Wq chunk0 (2-pass slot)

    // tokens -> xs: row 4g+s; s=0 CLS else z_{s-1}[seq0+g]
#pragma unroll
    for (int u = 0; u < 4; u++) {
        int idx = u * NTHR + tid, row = idx >> 5, c4 = (idx & 31) << 2;
        int g = row >> 2, s = row & 3;
        float4 v;
        if (s == 0) v = *(const float4*)(cls + c4);
        else {
            const float* zp = (s == 1) ? z0 : (s == 2) ? z1 : z2;
            v = *(const float4*)(zp + (long)(seq0 + g) * 128 + c4);
        }
        *(float4*)&sm->xs[row][c4] = v;
    }
    __syncthreads();
    conv_ax(sm, tid);

    float acc[4][4], facc[4][4];

    for (int l = 0; l < 2; l++) {
        int sb = 12 * l;
        // ---- QKV ----
        ZACC(acc); gemm(sm, sm->ax, sb + 0, sb + 1, acc, tid);
        epi_store(sm->qs, acc, bqkv + l * 384, tid);
        ZACC(acc); gemm(sm, sm->ax, sb + 1, sb + 2, acc, tid);
        epi_store(sm->ks, acc, bqkv + l * 384 + 128, tid);
        ZACC(acc); gemm(sm, sm->ax, sb + 2, sb + 3, acc, tid);
        epi_store(sm->vs, acc, bqkv + l * 384 + 256, tid);
        __syncthreads();

        // ---- attention: one thread per (seq, head); writes ax fp16 ----
        if (tid < 128) {
            int g = tid >> 3, h = tid & 7;
            int r0 = g * 4, co = h * 16;
            float sc[4][4];
#pragma unroll
            for (int i = 0; i < 4; i++)
#pragma unroll
                for (int j = 0; j < 4; j++) {
                    float s = 0.f;
#pragma unroll
                    for (int e = 0; e < 16; e++)
                        s += sm->qs[r0 + i][co + e] * sm->ks[r0 + j][co + e];
                    sc[i][j] = s * 0.25f;
                }
#pragma unroll
            for (int i = 0; i < 4; i++) {
                float m = fmaxf(fmaxf(sc[i][0], sc[i][1]), fmaxf(sc[i][2], sc[i][3]));
                float den = 0.f;
#pragma unroll
                for (int j = 0; j < 4; j++) { sc[i][j] = expf(sc[i][j] - m); den += sc[i][j]; }
                float inv = 1.f / den;
#pragma unroll
                for (int j = 0; j < 4; j++) sc[i][j] *= inv;
            }
#pragma unroll
            for (int i = 0; i < 4; i++)
#pragma unroll
                for (int e = 0; e < 16; e += 2) {
                    float o0 = 0.f, o1 = 0.f;
#pragma unroll
                    for (int j = 0; j < 4; j++) {
                        o0 += sc[i][j] * sm->vs[r0 + j][co + e];
                        o1 += sc[i][j] * sm->vs[r0 + j][co + e + 1];
                    }
                    st_ax(sm, r0 + i, co + e, o0, o1);
                }
        }
        // ax published by Wo gemm's chunk-0 barrier

        // ---- Wo + residual + LN1 ----
        ZACC(acc); gemm(sm, sm->ax, sb + 3, sb + 4, acc, tid);
        epi_resid(sm, acc, bo + l * 128, tid);
        __syncthreads();
        lnorm_conv(sm, ln1g + l * 128, ln1b + l * 128, tid);

        // ---- FFN ----
        ZACC(facc);
        for (int fc = 0; fc < 4; fc++) {
            ZACC(acc);
            gemm(sm, sm->ax, sb + 4 + 2 * fc, sb + 5 + 2 * fc, acc, tid);
            epi_gelu(sm, acc, b1 + l * 512 + fc * 128, tid);
            int nxt = (fc < 3) ? sb + 6 + 2 * fc : (l == 0 ? 12 : -1);
            gemm(sm, sm->cb, sb + 5 + 2 * fc, nxt, facc, tid);
        }
        epi_resid(sm, facc, b2 + l * 128, tid);
        __syncthreads();
        lnorm_conv(sm, ln2g + l * 128, ln2b + l * 128, tid);
        __syncthreads();
    }

    // CLS rows 4g -> out: 512 threads, one float4 each
    {
        int g = tid >> 5, c4 = (tid & 31) << 2;
        *(float4*)(out + (long)(seq0 + g) * 128 + c4) = *(float4*)&sm->xs[4 * g][c4];
    }
}

extern "C" void kernel_launch(void* const* d_in, const int* in_sizes, int n_in,
                              void* d_out, int out_size)
{
    (void)in_sizes; (void)n_in; (void)out_size;
    const float* z0   = (const float*)d_in[0];
    const float* z1   = (const float*)d_in[1];
    const float* z2   = (const float*)d_in[2];
    const float* cls  = (const float*)d_in[3];
    const float* Wqkv = (const float*)d_in[4];
    const float* bqkv = (const float*)d_in[5];
    const float* Wo   = (const float*)d_in[6];
    const float* bo   = (const float*)d_in[7];
    const float* W1   = (const float*)d_in[8];
    const float* b1   = (const float*)d_in[9];
    const float* W2   = (const float*)d_in[10];
    const float* b2   = (const float*)d_in[11];
    const float* ln1g = (const float*)d_in[12];
    const float* ln1b = (const float*)d_in[13];
    const float* ln2g = (const float*)d_in[14];
    const float* ln2b = (const float*)d_in[15];
    float* out = (float*)d_out;

    wsplit_kernel<<<(NTILE * 16384 + 383) / 384, 384>>>(Wqkv, Wo, W1, W2);

    cudaFuncSetAttribute(mixer_kernel,
                         cudaFuncAttributeMaxDynamicSharedMemorySize, (int)sizeof(SMem));
    mixer_kernel<<<NSEQ / GSEQ, NTHR, sizeof(SMem)>>>(
        z0, z1, z2, cls, bqkv, bo, b1, b2, ln1g, ln1b, ln2g, ln2b, out);
}